// round 7
// baseline (speedup 1.0000x reference)
#include <cuda_runtime.h>
#include <cuda_bf16.h>
#include <cstdint>
#include <mma.h>

using namespace nvcuda;

// Problem constants
#define B_  256
#define N_  256
#define L_  1024
#define D_  256
#define KQ_ 64
#define OUT_ 64

#define RESULT_ELEMS (B_ * N_ * OUT_)   // 4,194,304

// Scratch (device globals: allocation-free per harness rules)
__device__ float g_q[B_ * KQ_];                 // tf32-rounded
__device__ float g_kbuf[(size_t)N_ * L_ * KQ_]; // tf32-rounded, 67 MB
__device__ float g_vbuf[(size_t)N_ * L_ * OUT_];// tf32-rounded, 67 MB

// ---------------------------------------------------------------------------
// cp.async helpers (16B)
// ---------------------------------------------------------------------------
__device__ __forceinline__ void cp_async16(float* smem_dst, const float* gsrc)
{
    unsigned int s = (unsigned int)__cvta_generic_to_shared(smem_dst);
    asm volatile("cp.async.ca.shared.global [%0], [%1], 16;\n" :: "r"(s), "l"(gsrc));
}
__device__ __forceinline__ void cp_commit()
{
    asm volatile("cp.async.commit_group;\n");
}
__device__ __forceinline__ void cp_wait1()
{
    asm volatile("cp.async.wait_group 1;\n");
}
__device__ __forceinline__ void cp_wait0()
{
    asm volatile("cp.async.wait_group 0;\n");
}

__device__ __forceinline__ float4 tf32_round4(float4 v)
{
    v.x = wmma::__float_to_tf32(v.x);
    v.y = wmma::__float_to_tf32(v.y);
    v.z = wmma::__float_to_tf32(v.z);
    v.w = wmma::__float_to_tf32(v.w);
    return v;
}

// ---------------------------------------------------------------------------
// K0: q = queries @ Wq. 4 threads per output, shuffle reduce.
// ---------------------------------------------------------------------------
__global__ void qproj_kernel(const float* __restrict__ queries,
                             const float* __restrict__ Wq)
{
    int gt  = blockIdx.x * blockDim.x + threadIdx.x;   // 0 .. 65535
    int o   = gt >> 2;          // output index 0..16383
    int sub = gt & 3;           // K-split 0..3
    int b = o >> 6;
    int j = o & 63;
    float acc = 0.f;
    const float* qrow = queries + b * D_ + sub * 64;
    const float* wcol = Wq + (size_t)(sub * 64) * KQ_ + j;
#pragma unroll 16
    for (int d = 0; d < 64; d++)
        acc += qrow[d] * wcol[(size_t)d * KQ_];
    acc += __shfl_down_sync(0xffffffffu, acc, 2);
    acc += __shfl_down_sync(0xffffffffu, acc, 1);
    if (sub == 0)
        g_q[o] = wmma::__float_to_tf32(acc);
}

// ---------------------------------------------------------------------------
// K1: combined K/V projection. blockIdx.y: 0 -> keys@Wk, 1 -> values@Wv.
// ---------------------------------------------------------------------------
#define WLD 68
#define XLD 36
#define XSTG (128 * XLD)
#define PROJ_SMEM ((D_ * WLD + 2 * XSTG) * (int)sizeof(float))  // 106,496 B

__global__ __launch_bounds__(256, 2)
void proj_tf32_kernel(const float* __restrict__ keys,
                      const float* __restrict__ values,
                      const float* __restrict__ Wk,
                      const float* __restrict__ Wv,
                      float* __restrict__ kbuf,
                      float* __restrict__ vbuf)
{
    const float* X = (blockIdx.y == 0) ? keys : values;
    const float* W = (blockIdx.y == 0) ? Wk : Wv;
    float*       Y = (blockIdx.y == 0) ? kbuf : vbuf;

    extern __shared__ float psm[];
    float* s_w = psm;              // [256][WLD]
    float* s_x = psm + D_ * WLD;   // [2][128][XLD]

    const int tid = threadIdx.x;
    const int w  = tid >> 5;
    const int wr = w >> 1;   // 0..3
    const int wc = w & 1;    // 0..1
    const size_t row0 = (size_t)blockIdx.x * 128;

#pragma unroll
    for (int i = 0; i < 16; i++) {
        int e = i * 256 + tid;
        int r = e >> 4, c4 = e & 15;
        float4 v = *(const float4*)(W + (size_t)r * KQ_ + c4 * 4);
        *(float4*)(s_w + r * WLD + c4 * 4) = tf32_round4(v);
    }

#pragma unroll
    for (int i = 0; i < 4; i++) {
        int e = i * 256 + tid;
        int r = e >> 3, c4 = e & 7;
        cp_async16(s_x + r * XLD + c4 * 4, X + (row0 + r) * D_ + c4 * 4);
    }
    cp_commit();

    wmma::fragment<wmma::accumulator, 16, 16, 8, float> acc[2][2];
#pragma unroll
    for (int i = 0; i < 2; i++)
#pragma unroll
        for (int j = 0; j < 2; j++)
            wmma::fill_fragment(acc[i][j], 0.0f);

#pragma unroll 1
    for (int c = 0; c < 8; c++) {
        const int k0 = c * 32;
        if (c < 7) {
            float* dst = s_x + ((c + 1) & 1) * XSTG;
#pragma unroll
            for (int i = 0; i < 4; i++) {
                int e = i * 256 + tid;
                int r = e >> 3, c4 = e & 7;
                cp_async16(dst + r * XLD + c4 * 4,
                           X + (row0 + r) * D_ + k0 + 32 + c4 * 4);
            }
            cp_commit();
            cp_wait1();
        } else {
            cp_wait0();
        }
        __syncthreads();

        const float* xb = s_x + (c & 1) * XSTG;
#pragma unroll
        for (int ks = 0; ks < 4; ks++) {
            const int k = ks * 8;
            wmma::fragment<wmma::matrix_a, 16, 16, 8, wmma::precision::tf32, wmma::row_major> a[2];
            wmma::fragment<wmma::matrix_b, 16, 16, 8, wmma::precision::tf32, wmma::row_major> b[2];
#pragma unroll
            for (int i = 0; i < 2; i++) {
                wmma::load_matrix_sync(a[i], xb + (wr * 32 + i * 16) * XLD + k, XLD);
#pragma unroll
                for (int t = 0; t < a[i].num_elements; t++)
                    a[i].x[t] = wmma::__float_to_tf32(a[i].x[t]);
            }
#pragma unroll
            for (int j = 0; j < 2; j++)
                wmma::load_matrix_sync(b[j], s_w + (k0 + k) * WLD + wc * 32 + j * 16, WLD);
#pragma unroll
            for (int i = 0; i < 2; i++)
#pragma unroll
                for (int j = 0; j < 2; j++)
                    wmma::mma_sync(acc[i][j], a[i], b[j], acc[i][j]);
        }
        __syncthreads();
    }

#pragma unroll
    for (int i = 0; i < 2; i++)
#pragma unroll
        for (int j = 0; j < 2; j++) {
#pragma unroll
            for (int t = 0; t < acc[i][j].num_elements; t++)
                acc[i][j].x[t] = wmma::__float_to_tf32(acc[i][j].x[t]);
            wmma::store_matrix_sync(Y + (row0 + wr * 32 + i * 16) * KQ_ + wc * 32 + j * 16,
                                    acc[i][j], KQ_, wmma::mem_row_major);
        }
}

// ---------------------------------------------------------------------------
// K2: fused streaming attention. Block = 128 b-rows x one n. 512 thr, 2 CTA/SM.
// L-chunk = 64. Per chunk: QK mma (warp 32x16, 2 accs) -> exp -> E to smem +
// unnormalized attn write + reg rowsums -> PV mma (warp 32x16, 2 persistent).
// ---------------------------------------------------------------------------
#define QLDS 68
#define KLDS 68
#define ELDS 68
#define SQ_OFF 0
#define SK_OFF (128 * QLDS)               //  8704
#define SV_OFF (SK_OFF + 64 * KLDS)       // 13056
#define SE_OFF (SV_OFF + 64 * KLDS)       // 17408
#define SI_OFF (SE_OFF + 128 * ELDS)      // 26112
#define ATTN_SMEM ((SI_OFF + 128) * (int)sizeof(float))   // 104,960 B

__global__ __launch_bounds__(512, 2)
void attn_kernel(float* __restrict__ out)
{
    extern __shared__ float smem[];
    float* s_q   = smem + SQ_OFF;   // [128][QLDS] q tile (tf32)
    float* s_k   = smem + SK_OFF;   // [64][KLDS] kb chunk
    float* s_v   = smem + SV_OFF;   // [64][KLDS] vb chunk
    float* s_e   = smem + SE_OFF;   // [128][ELDS] E chunk (tf32(exp))
    float* s_inv = smem + SI_OFF;   // [128] 1/rowsum

    const int n   = blockIdx.y;
    const int b0  = blockIdx.x * 128;
    const int tid = threadIdx.x;
    const int w    = tid >> 5;
    const int lane = tid & 31;

    const float* kb = g_kbuf + (size_t)n * L_ * KQ_;
    const float* vb = g_vbuf + (size_t)n * L_ * OUT_;
    float* attn_out = out + RESULT_ELEMS + ((size_t)n * B_ + b0) * L_;

    // Prologue: stage q tile (128x64) + kb chunk 0, one commit group.
#pragma unroll
    for (int i = 0; i < 4; i++) {
        int e = i * 512 + tid;
        int r = e >> 4, c4 = e & 15;
        cp_async16(s_q + r * QLDS + c4 * 4, g_q + (size_t)(b0 + r) * KQ_ + c4 * 4);
    }
#pragma unroll
    for (int i = 0; i < 2; i++) {
        int e = i * 512 + tid;
        int r = e >> 4, c4 = e & 15;
        cp_async16(s_k + r * KLDS + c4 * 4, kb + (size_t)r * KQ_ + c4 * 4);
    }
    cp_commit();

    // warp grid 4x4 for both phases: rows 32, cols 16
    const int wr = w >> 2;   // 0..3
    const int wc = w & 3;    // 0..3

    wmma::fragment<wmma::accumulator, 16, 16, 8, float> pacc[2];
#pragma unroll
    for (int i = 0; i < 2; i++) wmma::fill_fragment(pacc[i], 0.0f);

    float rs[8];
#pragma unroll
    for (int i = 0; i < 8; i++) rs[i] = 0.f;

#pragma unroll 1
    for (int c = 0; c < 16; c++) {
        const int l0 = c * 64;

        // issue vb_c into s_v (overlaps QK mma)
#pragma unroll
        for (int i = 0; i < 2; i++) {
            int e = i * 512 + tid;
            int r = e >> 4, c4 = e & 15;
            cp_async16(s_v + r * KLDS + c4 * 4,
                       vb + (size_t)(l0 + r) * OUT_ + c4 * 4);
        }
        cp_commit();
        cp_wait1();          // kb_c (and q on first iter) arrived
        __syncthreads();

        // ---- QK mma: E tile 32x16 per warp ----
        wmma::fragment<wmma::accumulator, 16, 16, 8, float> eacc[2];
#pragma unroll
        for (int i = 0; i < 2; i++) wmma::fill_fragment(eacc[i], 0.0f);

#pragma unroll
        for (int ks = 0; ks < 8; ks++) {
            const int k = ks * 8;
            wmma::fragment<wmma::matrix_a, 16, 16, 8, wmma::precision::tf32, wmma::row_major> a[2];
            wmma::fragment<wmma::matrix_b, 16, 16, 8, wmma::precision::tf32, wmma::col_major> b;
#pragma unroll
            for (int i = 0; i < 2; i++)
                wmma::load_matrix_sync(a[i], s_q + (wr * 32 + i * 16) * QLDS + k, QLDS);
            wmma::load_matrix_sync(b, s_k + (wc * 16) * KLDS + k, KLDS);
#pragma unroll
            for (int i = 0; i < 2; i++)
                wmma::mma_sync(eacc[i], a[i], b, eacc[i]);
        }

        // exp + tf32 round, park in s_e
#pragma unroll
        for (int i = 0; i < 2; i++) {
#pragma unroll
            for (int t = 0; t < eacc[i].num_elements; t++)
                eacc[i].x[t] = wmma::__float_to_tf32(__expf(eacc[i].x[t] * 0.125f));
            wmma::store_matrix_sync(s_e + (wr * 32 + i * 16) * ELDS + wc * 16,
                                    eacc[i], ELDS, wmma::mem_row_major);
        }
        __syncthreads();     // s_e ready; s_k free

        // issue kb_{c+1} into s_k (overlaps rowsum + PV mma)
        if (c < 15) {
            const float* src = kb + (size_t)(l0 + 64) * KQ_;
#pragma unroll
            for (int i = 0; i < 2; i++) {
                int e = i * 512 + tid;
                int r = e >> 4, c4 = e & 15;
                cp_async16(s_k + r * KLDS + c4 * 4, src + (size_t)r * KQ_ + c4 * 4);
            }
            cp_commit();
        }

        // ---- rowsums + unnormalized attn write (warp w owns rows w*8..w*8+7)
#pragma unroll
        for (int i = 0; i < 8; i++) {
            const int r = w * 8 + i;
            const float* row = s_e + r * ELDS;
            float* arow = attn_out + (size_t)r * L_ + l0;
            float e0 = row[lane];
            float e1 = row[32 + lane];
            rs[i] += e0 + e1;
            arow[lane] = e0;
            arow[32 + lane] = e1;
        }

        if (c < 15) cp_wait1(); else cp_wait0();   // vb_c arrived
        __syncthreads();

        // ---- PV mma: result tile 32x16 per warp, accumulate across chunks ----
#pragma unroll
        for (int ks = 0; ks < 8; ks++) {
            const int k = ks * 8;
            wmma::fragment<wmma::matrix_a, 16, 16, 8, wmma::precision::tf32, wmma::row_major> a[2];
            wmma::fragment<wmma::matrix_b, 16, 16, 8, wmma::precision::tf32, wmma::row_major> b;
#pragma unroll
            for (int i = 0; i < 2; i++)
                wmma::load_matrix_sync(a[i], s_e + (wr * 32 + i * 16) * ELDS + k, ELDS);
            wmma::load_matrix_sync(b, s_v + k * KLDS + wc * 16, KLDS);
#pragma unroll
            for (int i = 0; i < 2; i++)
                wmma::mma_sync(pacc[i], a[i], b, pacc[i]);
        }
        __syncthreads();     // s_e / s_v free for next chunk
    }

    // ---- epilogue: rowsum reduce ----
#pragma unroll
    for (int i = 0; i < 8; i++) {
        float s = rs[i];
#pragma unroll
        for (int off = 16; off; off >>= 1)
            s += __shfl_xor_sync(0xffffffffu, s, off);
        if (lane == 0) s_inv[w * 8 + i] = 1.0f / s;
    }
    // park PV accumulators in s_e as [128][ELDS]
#pragma unroll
    for (int i = 0; i < 2; i++)
        wmma::store_matrix_sync(s_e + (wr * 32 + i * 16) * ELDS + wc * 16,
                                pacc[i], ELDS, wmma::mem_row_major);
    __syncthreads();

    // scaled result write: out[(b0+r)*N*64 + n*64 + c]
#pragma unroll
    for (int it = 0; it < 4; it++) {
        int e = it * 512 + tid;
        int r = e >> 4, c4 = e & 15;
        const float inv = s_inv[r];
        float4 v = *(float4*)(s_e + r * ELDS + c4 * 4);
        v.x *= inv; v.y *= inv; v.z *= inv; v.w *= inv;
        *(float4*)(out + ((size_t)(b0 + r) * N_ + n) * OUT_ + c4 * 4) = v;
    }

    // in-place attn normalization (128 x 1024 RMW, coalesced)
#pragma unroll 1
    for (int it = 0; it < 64; it++) {
        int e = it * 512 + tid;
        int r = e >> 8, c4 = e & 255;
        const float inv = s_inv[r];
        float4* p = (float4*)(attn_out + (size_t)r * L_ + c4 * 4);
        float4 v = *p;
        v.x *= inv; v.y *= inv; v.z *= inv; v.w *= inv;
        *p = v;
    }
}

// ---------------------------------------------------------------------------
extern "C" void kernel_launch(void* const* d_in, const int* in_sizes, int n_in,
                              void* d_out, int out_size)
{
    const float* queries = (const float*)d_in[0];
    const float* keys    = (const float*)d_in[1];
    const float* values  = (const float*)d_in[2];
    const float* Wq      = (const float*)d_in[3];
    const float* Wk      = (const float*)d_in[4];
    const float* Wv      = (const float*)d_in[5];
    float* out = (float*)d_out;

    cudaFuncSetAttribute(attn_kernel,
                         cudaFuncAttributeMaxDynamicSharedMemorySize, ATTN_SMEM);
    cudaFuncSetAttribute(proj_tf32_kernel,
                         cudaFuncAttributeMaxDynamicSharedMemorySize, PROJ_SMEM);

    float *kbuf_ptr, *vbuf_ptr;
    cudaGetSymbolAddress((void**)&kbuf_ptr, g_kbuf);
    cudaGetSymbolAddress((void**)&vbuf_ptr, g_vbuf);

    // K0: q projection (4 threads/output)
    qproj_kernel<<<(B_ * KQ_ * 4) / 256, 256>>>(queries, Wq);

    // K1: combined key/value projections
    dim3 pgrid((N_ * L_) / 128, 2);   // (2048, 2)
    proj_tf32_kernel<<<pgrid, 256, PROJ_SMEM>>>(keys, values, Wk, Wv,
                                                kbuf_ptr, vbuf_ptr);

    // K2: fused attention
    dim3 grid(B_ / 128, N_);   // (2, 256)
    attn_kernel<<<grid, 512, ATTN_SMEM>>>(out);
}

// round 8
// speedup vs baseline: 1.5538x; 1.5538x over previous
#include <cuda_runtime.h>
#include <cuda_bf16.h>
#include <cstdint>
#include <mma.h>

using namespace nvcuda;

// Problem constants
#define B_  256
#define N_  256
#define L_  1024
#define D_  256
#define KQ_ 64
#define OUT_ 64

#define RESULT_ELEMS (B_ * N_ * OUT_)   // 4,194,304

// Scratch (device globals: allocation-free per harness rules)
__device__ float g_q[B_ * KQ_];                 // tf32-rounded
__device__ float g_kbuf[(size_t)N_ * L_ * KQ_]; // tf32-rounded, 67 MB
__device__ float g_vbuf[(size_t)N_ * L_ * OUT_];// tf32-rounded, 67 MB

// ---------------------------------------------------------------------------
// cp.async helpers (16B)
// ---------------------------------------------------------------------------
__device__ __forceinline__ void cp_async16(float* smem_dst, const float* gsrc)
{
    unsigned int s = (unsigned int)__cvta_generic_to_shared(smem_dst);
    asm volatile("cp.async.ca.shared.global [%0], [%1], 16;\n" :: "r"(s), "l"(gsrc));
}
__device__ __forceinline__ void cp_commit()
{
    asm volatile("cp.async.commit_group;\n");
}
__device__ __forceinline__ void cp_wait1()
{
    asm volatile("cp.async.wait_group 1;\n");
}
__device__ __forceinline__ void cp_wait0()
{
    asm volatile("cp.async.wait_group 0;\n");
}

__device__ __forceinline__ float4 tf32_round4(float4 v)
{
    v.x = wmma::__float_to_tf32(v.x);
    v.y = wmma::__float_to_tf32(v.y);
    v.z = wmma::__float_to_tf32(v.z);
    v.w = wmma::__float_to_tf32(v.w);
    return v;
}

// ---------------------------------------------------------------------------
// K1: combined K/V projection + fused q projection.
// blockIdx.y: 0 -> keys@Wk, 1 -> values@Wv.
// Blocks (y==0, x<16) additionally compute a 1024-output slice of
// q = queries @ Wq (fp32, tf32-rounded) before their projection work.
// ---------------------------------------------------------------------------
#define WLD 68
#define XLD 36
#define XSTG (128 * XLD)
#define PROJ_SMEM ((D_ * WLD + 2 * XSTG) * (int)sizeof(float))  // 106,496 B

__global__ __launch_bounds__(256, 2)
void proj_tf32_kernel(const float* __restrict__ queries,
                      const float* __restrict__ keys,
                      const float* __restrict__ values,
                      const float* __restrict__ Wq,
                      const float* __restrict__ Wk,
                      const float* __restrict__ Wv,
                      float* __restrict__ kbuf,
                      float* __restrict__ vbuf)
{
    const int tid = threadIdx.x;

    // ---- fused q projection (16 blocks, 1024 outputs each) ----
    if (blockIdx.y == 0 && blockIdx.x < 16) {
        const int base = blockIdx.x * 1024;
#pragma unroll
        for (int i = 0; i < 4; i++) {
            int o = base + i * 256 + tid;
            int b = o >> 6, j = o & 63;
            float acc = 0.f;
            const float* qrow = queries + b * D_;
            const float* wcol = Wq + j;
#pragma unroll 8
            for (int d = 0; d < D_; d++)
                acc += qrow[d] * wcol[(size_t)d * KQ_];
            g_q[o] = wmma::__float_to_tf32(acc);
        }
    }

    const float* X = (blockIdx.y == 0) ? keys : values;
    const float* W = (blockIdx.y == 0) ? Wk : Wv;
    float*       Y = (blockIdx.y == 0) ? kbuf : vbuf;

    extern __shared__ float psm[];
    float* s_w = psm;              // [256][WLD]
    float* s_x = psm + D_ * WLD;   // [2][128][XLD]

    const int w  = tid >> 5;
    const int wr = w >> 1;   // 0..3
    const int wc = w & 1;    // 0..1
    const size_t row0 = (size_t)blockIdx.x * 128;

    // Stage all of W (256x64), rounded to tf32.
#pragma unroll
    for (int i = 0; i < 16; i++) {
        int e = i * 256 + tid;
        int r = e >> 4, c4 = e & 15;
        float4 v = *(const float4*)(W + (size_t)r * KQ_ + c4 * 4);
        *(float4*)(s_w + r * WLD + c4 * 4) = tf32_round4(v);
    }

    // Prefetch X chunk 0 (raw; rounded at fragment load)
#pragma unroll
    for (int i = 0; i < 4; i++) {
        int e = i * 256 + tid;
        int r = e >> 3, c4 = e & 7;
        cp_async16(s_x + r * XLD + c4 * 4, X + (row0 + r) * D_ + c4 * 4);
    }
    cp_commit();

    wmma::fragment<wmma::accumulator, 16, 16, 8, float> acc[2][2];
#pragma unroll
    for (int i = 0; i < 2; i++)
#pragma unroll
        for (int j = 0; j < 2; j++)
            wmma::fill_fragment(acc[i][j], 0.0f);

#pragma unroll 1
    for (int c = 0; c < 8; c++) {
        const int k0 = c * 32;
        if (c < 7) {
            float* dst = s_x + ((c + 1) & 1) * XSTG;
#pragma unroll
            for (int i = 0; i < 4; i++) {
                int e = i * 256 + tid;
                int r = e >> 3, c4 = e & 7;
                cp_async16(dst + r * XLD + c4 * 4,
                           X + (row0 + r) * D_ + k0 + 32 + c4 * 4);
            }
            cp_commit();
            cp_wait1();
        } else {
            cp_wait0();
        }
        __syncthreads();

        const float* xb = s_x + (c & 1) * XSTG;
#pragma unroll
        for (int ks = 0; ks < 4; ks++) {
            const int k = ks * 8;
            wmma::fragment<wmma::matrix_a, 16, 16, 8, wmma::precision::tf32, wmma::row_major> a[2];
            wmma::fragment<wmma::matrix_b, 16, 16, 8, wmma::precision::tf32, wmma::row_major> b[2];
#pragma unroll
            for (int i = 0; i < 2; i++) {
                wmma::load_matrix_sync(a[i], xb + (wr * 32 + i * 16) * XLD + k, XLD);
#pragma unroll
                for (int t = 0; t < a[i].num_elements; t++)
                    a[i].x[t] = wmma::__float_to_tf32(a[i].x[t]);
            }
#pragma unroll
            for (int j = 0; j < 2; j++)
                wmma::load_matrix_sync(b[j], s_w + (k0 + k) * WLD + wc * 32 + j * 16, WLD);
#pragma unroll
            for (int i = 0; i < 2; i++)
#pragma unroll
                for (int j = 0; j < 2; j++)
                    wmma::mma_sync(acc[i][j], a[i], b[j], acc[i][j]);
        }
        __syncthreads();
    }

#pragma unroll
    for (int i = 0; i < 2; i++)
#pragma unroll
        for (int j = 0; j < 2; j++) {
#pragma unroll
            for (int t = 0; t < acc[i][j].num_elements; t++)
                acc[i][j].x[t] = wmma::__float_to_tf32(acc[i][j].x[t]);
            wmma::store_matrix_sync(Y + (row0 + wr * 32 + i * 16) * KQ_ + wc * 32 + j * 16,
                                    acc[i][j], KQ_, wmma::mem_row_major);
        }
}

// ---------------------------------------------------------------------------
// K2: fused streaming attention (proven R6 config).
// Block = 128 b-rows x one n. 512 threads, 1 CTA/SM, L-chunk 128.
// Per chunk: QK mma (warp 32x32, 4 indep accs) -> exp -> E to smem +
// unnormalized attn write + reg rowsums -> PV mma (warp 32x16, 2 persistent).
// ---------------------------------------------------------------------------
#define QLDS 68
#define KLDS 68
#define ELDS 132
#define SQ_OFF 0
#define SK_OFF (128 * QLDS)               // 8704
#define SV_OFF (SK_OFF + 128 * KLDS)      // 17408
#define SE_OFF (SV_OFF + 128 * KLDS)      // 26112
#define SI_OFF (SE_OFF + 128 * ELDS)      // 43008
#define ATTN_SMEM ((SI_OFF + 128) * (int)sizeof(float))   // 172,544 B

__global__ __launch_bounds__(512)
void attn_kernel(float* __restrict__ out)
{
    extern __shared__ float smem[];
    float* s_q   = smem + SQ_OFF;   // [128][QLDS] q tile (tf32)
    float* s_k   = smem + SK_OFF;   // [128][KLDS] kb chunk
    float* s_v   = smem + SV_OFF;   // [128][KLDS] vb chunk
    float* s_e   = smem + SE_OFF;   // [128][ELDS] E chunk (tf32(exp))
    float* s_inv = smem + SI_OFF;   // [128] 1/rowsum

    const int n   = blockIdx.y;
    const int b0  = blockIdx.x * 128;
    const int tid = threadIdx.x;
    const int w    = tid >> 5;
    const int lane = tid & 31;

    const float* kb = g_kbuf + (size_t)n * L_ * KQ_;
    const float* vb = g_vbuf + (size_t)n * L_ * OUT_;
    float* attn_out = out + RESULT_ELEMS + ((size_t)n * B_ + b0) * L_;

    // Prologue: stage q tile (128x64) + kb chunk 0, one commit group.
#pragma unroll
    for (int i = 0; i < 4; i++) {
        int e = i * 512 + tid;
        int r = e >> 4, c4 = e & 15;
        cp_async16(s_q + r * QLDS + c4 * 4, g_q + (size_t)(b0 + r) * KQ_ + c4 * 4);
        cp_async16(s_k + r * KLDS + c4 * 4, kb + (size_t)r * KQ_ + c4 * 4);
    }
    cp_commit();

    // E-phase warp grid: 4 rows x 4 cols, tile 32x32 (4 indep accumulators)
    const int ewr = w >> 2;   // 0..3
    const int ewc = w & 3;    // 0..3
    // PV warp grid: 4 rows x 4 cols, tile 32x16 (2 persistent accumulators)
    const int pwr = w >> 2;
    const int pwc = w & 3;

    wmma::fragment<wmma::accumulator, 16, 16, 8, float> pacc[2];
#pragma unroll
    for (int i = 0; i < 2; i++) wmma::fill_fragment(pacc[i], 0.0f);

    float rs[8];
#pragma unroll
    for (int i = 0; i < 8; i++) rs[i] = 0.f;

#pragma unroll 1
    for (int c = 0; c < 8; c++) {
        const int l0 = c * 128;

        // issue vb_c into s_v (overlaps with E mma below)
#pragma unroll
        for (int i = 0; i < 4; i++) {
            int e = i * 512 + tid;
            int r = e >> 4, c4 = e & 15;
            cp_async16(s_v + r * KLDS + c4 * 4,
                       vb + (size_t)(l0 + r) * OUT_ + c4 * 4);
        }
        cp_commit();
        cp_wait1();          // kb_c (and q on first iter) arrived
        __syncthreads();

        // ---- QK mma: E tile 32x32 per warp ----
        wmma::fragment<wmma::accumulator, 16, 16, 8, float> eacc[2][2];
#pragma unroll
        for (int i = 0; i < 2; i++)
#pragma unroll
            for (int j = 0; j < 2; j++)
                wmma::fill_fragment(eacc[i][j], 0.0f);

#pragma unroll
        for (int ks = 0; ks < 8; ks++) {
            const int k = ks * 8;
            wmma::fragment<wmma::matrix_a, 16, 16, 8, wmma::precision::tf32, wmma::row_major> a[2];
            wmma::fragment<wmma::matrix_b, 16, 16, 8, wmma::precision::tf32, wmma::col_major> b[2];
#pragma unroll
            for (int i = 0; i < 2; i++)
                wmma::load_matrix_sync(a[i], s_q + (ewr * 32 + i * 16) * QLDS + k, QLDS);
#pragma unroll
            for (int j = 0; j < 2; j++)
                wmma::load_matrix_sync(b[j], s_k + (ewc * 32 + j * 16) * KLDS + k, KLDS);
#pragma unroll
            for (int i = 0; i < 2; i++)
#pragma unroll
                for (int j = 0; j < 2; j++)
                    wmma::mma_sync(eacc[i][j], a[i], b[j], eacc[i][j]);
        }

        // exp + tf32 round, park in s_e
#pragma unroll
        for (int i = 0; i < 2; i++)
#pragma unroll
            for (int j = 0; j < 2; j++) {
#pragma unroll
                for (int t = 0; t < eacc[i][j].num_elements; t++)
                    eacc[i][j].x[t] =
                        wmma::__float_to_tf32(__expf(eacc[i][j].x[t] * 0.125f));
                wmma::store_matrix_sync(
                    s_e + (ewr * 32 + i * 16) * ELDS + ewc * 32 + j * 16,
                    eacc[i][j], ELDS, wmma::mem_row_major);
            }
        __syncthreads();     // s_e ready; s_k free

        // issue kb_{c+1} into s_k (overlaps rowsum + PV mma)
        if (c < 7) {
            const float* src = kb + (size_t)(l0 + 128) * KQ_;
#pragma unroll
            for (int i = 0; i < 4; i++) {
                int e = i * 512 + tid;
                int r = e >> 4, c4 = e & 15;
                cp_async16(s_k + r * KLDS + c4 * 4, src + (size_t)r * KQ_ + c4 * 4);
            }
            cp_commit();
        }

        // ---- rowsums + unnormalized attn write (warp w owns rows w*8..w*8+7)
#pragma unroll
        for (int i = 0; i < 8; i++) {
            const int r = w * 8 + i;
            const float* row = s_e + r * ELDS;
            float* arow = attn_out + (size_t)r * L_ + l0;
#pragma unroll
            for (int l = 0; l < 128; l += 32) {
                float e = row[l + lane];
                rs[i] += e;
                arow[l + lane] = e;
            }
        }

        if (c < 7) cp_wait1(); else cp_wait0();   // vb_c arrived
        __syncthreads();

        // ---- PV mma: result tile 32x16 per warp, accumulate across chunks ----
#pragma unroll
        for (int ks = 0; ks < 16; ks++) {
            const int k = ks * 8;
            wmma::fragment<wmma::matrix_a, 16, 16, 8, wmma::precision::tf32, wmma::row_major> a[2];
            wmma::fragment<wmma::matrix_b, 16, 16, 8, wmma::precision::tf32, wmma::row_major> b;
#pragma unroll
            for (int i = 0; i < 2; i++)
                wmma::load_matrix_sync(a[i], s_e + (pwr * 32 + i * 16) * ELDS + k, ELDS);
            wmma::load_matrix_sync(b, s_v + k * KLDS + pwc * 16, KLDS);
#pragma unroll
            for (int i = 0; i < 2; i++)
                wmma::mma_sync(pacc[i], a[i], b, pacc[i]);
        }
        __syncthreads();     // s_e / s_v free for next chunk
    }

    // ---- epilogue: rowsum reduce ----
#pragma unroll
    for (int i = 0; i < 8; i++) {
        float s = rs[i];
#pragma unroll
        for (int off = 16; off; off >>= 1)
            s += __shfl_xor_sync(0xffffffffu, s, off);
        if (lane == 0) s_inv[w * 8 + i] = 1.0f / s;
    }
    // park PV accumulators in s_e as [128][68]
#pragma unroll
    for (int i = 0; i < 2; i++)
        wmma::store_matrix_sync(s_e + (pwr * 32 + i * 16) * 68 + pwc * 16,
                                pacc[i], 68, wmma::mem_row_major);
    __syncthreads();

    // scaled result write: out[(b0+r)*N*64 + n*64 + c]
#pragma unroll
    for (int it = 0; it < 4; it++) {
        int e = it * 512 + tid;
        int r = e >> 4, c4 = e & 15;
        const float inv = s_inv[r];
        float4 v = *(float4*)(s_e + r * 68 + c4 * 4);
        v.x *= inv; v.y *= inv; v.z *= inv; v.w *= inv;
        *(float4*)(out + ((size_t)(b0 + r) * N_ + n) * OUT_ + c4 * 4) = v;
    }

    // in-place attn normalization (128 x 1024 RMW, coalesced)
#pragma unroll 1
    for (int it = 0; it < 64; it++) {
        int e = it * 512 + tid;
        int r = e >> 8, c4 = e & 255;
        const float inv = s_inv[r];
        float4* p = (float4*)(attn_out + (size_t)r * L_ + c4 * 4);
        float4 v = *p;
        v.x *= inv; v.y *= inv; v.z *= inv; v.w *= inv;
        *p = v;
    }
}

// ---------------------------------------------------------------------------
extern "C" void kernel_launch(void* const* d_in, const int* in_sizes, int n_in,
                              void* d_out, int out_size)
{
    const float* queries = (const float*)d_in[0];
    const float* keys    = (const float*)d_in[1];
    const float* values  = (const float*)d_in[2];
    const float* Wq      = (const float*)d_in[3];
    const float* Wk      = (const float*)d_in[4];
    const float* Wv      = (const float*)d_in[5];
    float* out = (float*)d_out;

    cudaFuncSetAttribute(attn_kernel,
                         cudaFuncAttributeMaxDynamicSharedMemorySize, ATTN_SMEM);
    cudaFuncSetAttribute(proj_tf32_kernel,
                         cudaFuncAttributeMaxDynamicSharedMemorySize, PROJ_SMEM);

    float *kbuf_ptr, *vbuf_ptr;
    cudaGetSymbolAddress((void**)&kbuf_ptr, g_kbuf);
    cudaGetSymbolAddress((void**)&vbuf_ptr, g_vbuf);

    // K1: combined key/value projections + fused q projection
    dim3 pgrid((N_ * L_) / 128, 2);   // (2048, 2)
    proj_tf32_kernel<<<pgrid, 256, PROJ_SMEM>>>(queries, keys, values,
                                                Wq, Wk, Wv, kbuf_ptr, vbuf_ptr);

    // K2: fused attention
    dim3 grid(B_ / 128, N_);   // (2, 256)
    attn_kernel<<<grid, 512, ATTN_SMEM>>>(out);
}

// round 9
// speedup vs baseline: 2.3630x; 1.5208x over previous
#include <cuda_runtime.h>
#include <cuda_fp16.h>
#include <cuda_bf16.h>
#include <cstdint>
#include <mma.h>

using namespace nvcuda;

// Problem constants
#define B_  256
#define N_  256
#define L_  1024
#define D_  256
#define KQ_ 64
#define OUT_ 64

#define RESULT_ELEMS (B_ * N_ * OUT_)   // 4,194,304

// Scratch (device globals: allocation-free per harness rules) — fp16
__device__ __half g_q[B_ * KQ_];
__device__ __half g_kbuf[(size_t)N_ * L_ * KQ_];  // 33.5 MB
__device__ __half g_vbuf[(size_t)N_ * L_ * OUT_]; // 33.5 MB

// ---------------------------------------------------------------------------
// cp.async helpers (16B)
// ---------------------------------------------------------------------------
__device__ __forceinline__ void cp_async16(void* smem_dst, const void* gsrc)
{
    unsigned int s = (unsigned int)__cvta_generic_to_shared(smem_dst);
    asm volatile("cp.async.ca.shared.global [%0], [%1], 16;\n" :: "r"(s), "l"(gsrc));
}
__device__ __forceinline__ void cp_commit()
{
    asm volatile("cp.async.commit_group;\n");
}
__device__ __forceinline__ void cp_wait1()
{
    asm volatile("cp.async.wait_group 1;\n");
}
__device__ __forceinline__ void cp_wait0()
{
    asm volatile("cp.async.wait_group 0;\n");
}

__device__ __forceinline__ float4 tf32_round4(float4 v)
{
    v.x = wmma::__float_to_tf32(v.x);
    v.y = wmma::__float_to_tf32(v.y);
    v.z = wmma::__float_to_tf32(v.z);
    v.w = wmma::__float_to_tf32(v.w);
    return v;
}

// ---------------------------------------------------------------------------
// K1: combined K/V projection (TF32 internally) + fused q projection.
// Outputs stored as fp16. blockIdx.y: 0 -> keys@Wk, 1 -> values@Wv.
// ---------------------------------------------------------------------------
#define WLD 68
#define XLD 36
#define XSTG (128 * XLD)
#define PROJ_SMEM ((D_ * WLD + 2 * XSTG) * (int)sizeof(float))  // 106,496 B

__global__ __launch_bounds__(256, 2)
void proj_tf32_kernel(const float* __restrict__ queries,
                      const float* __restrict__ keys,
                      const float* __restrict__ values,
                      const float* __restrict__ Wq,
                      const float* __restrict__ Wk,
                      const float* __restrict__ Wv,
                      __half* __restrict__ kbuf,
                      __half* __restrict__ vbuf)
{
    const int tid = threadIdx.x;

    // ---- fused q projection (16 blocks, 1024 outputs each), fp32 acc ----
    if (blockIdx.y == 0 && blockIdx.x < 16) {
        const int base = blockIdx.x * 1024;
#pragma unroll
        for (int i = 0; i < 4; i++) {
            int o = base + i * 256 + tid;
            int b = o >> 6, j = o & 63;
            float acc = 0.f;
            const float* qrow = queries + b * D_;
            const float* wcol = Wq + j;
#pragma unroll 8
            for (int d = 0; d < D_; d++)
                acc += qrow[d] * wcol[(size_t)d * KQ_];
            g_q[o] = __float2half(acc);
        }
    }

    const float* X = (blockIdx.y == 0) ? keys : values;
    const float* W = (blockIdx.y == 0) ? Wk : Wv;
    __half*      Y = (blockIdx.y == 0) ? kbuf : vbuf;

    extern __shared__ float psm[];
    float* s_w = psm;              // [256][WLD]
    float* s_x = psm + D_ * WLD;   // [2][128][XLD]

    const int w  = tid >> 5;
    const int wr = w >> 1;   // 0..3
    const int wc = w & 1;    // 0..1
    const size_t row0 = (size_t)blockIdx.x * 128;

    // Stage all of W (256x64), rounded to tf32.
#pragma unroll
    for (int i = 0; i < 16; i++) {
        int e = i * 256 + tid;
        int r = e >> 4, c4 = e & 15;
        float4 v = *(const float4*)(W + (size_t)r * KQ_ + c4 * 4);
        *(float4*)(s_w + r * WLD + c4 * 4) = tf32_round4(v);
    }

    // Prefetch X chunk 0
#pragma unroll
    for (int i = 0; i < 4; i++) {
        int e = i * 256 + tid;
        int r = e >> 3, c4 = e & 7;
        cp_async16(s_x + r * XLD + c4 * 4, X + (row0 + r) * D_ + c4 * 4);
    }
    cp_commit();

    wmma::fragment<wmma::accumulator, 16, 16, 8, float> acc[2][2];
#pragma unroll
    for (int i = 0; i < 2; i++)
#pragma unroll
        for (int j = 0; j < 2; j++)
            wmma::fill_fragment(acc[i][j], 0.0f);

#pragma unroll 1
    for (int c = 0; c < 8; c++) {
        const int k0 = c * 32;
        if (c < 7) {
            float* dst = s_x + ((c + 1) & 1) * XSTG;
#pragma unroll
            for (int i = 0; i < 4; i++) {
                int e = i * 256 + tid;
                int r = e >> 3, c4 = e & 7;
                cp_async16(dst + r * XLD + c4 * 4,
                           X + (row0 + r) * D_ + k0 + 32 + c4 * 4);
            }
            cp_commit();
            cp_wait1();
        } else {
            cp_wait0();
        }
        __syncthreads();

        const float* xb = s_x + (c & 1) * XSTG;
#pragma unroll
        for (int ks = 0; ks < 4; ks++) {
            const int k = ks * 8;
            wmma::fragment<wmma::matrix_a, 16, 16, 8, wmma::precision::tf32, wmma::row_major> a[2];
            wmma::fragment<wmma::matrix_b, 16, 16, 8, wmma::precision::tf32, wmma::row_major> b[2];
#pragma unroll
            for (int i = 0; i < 2; i++) {
                wmma::load_matrix_sync(a[i], xb + (wr * 32 + i * 16) * XLD + k, XLD);
#pragma unroll
                for (int t = 0; t < a[i].num_elements; t++)
                    a[i].x[t] = wmma::__float_to_tf32(a[i].x[t]);
            }
#pragma unroll
            for (int j = 0; j < 2; j++)
                wmma::load_matrix_sync(b[j], s_w + (k0 + k) * WLD + wc * 32 + j * 16, WLD);
#pragma unroll
            for (int i = 0; i < 2; i++)
#pragma unroll
                for (int j = 0; j < 2; j++)
                    wmma::mma_sync(acc[i][j], a[i], b[j], acc[i][j]);
        }
        __syncthreads();
    }

    // Epilogue: park fp32 results in s_x [128][68], then convert-write fp16.
#pragma unroll
    for (int i = 0; i < 2; i++)
#pragma unroll
        for (int j = 0; j < 2; j++)
            wmma::store_matrix_sync(s_x + (wr * 32 + i * 16) * 68 + wc * 32 + j * 16,
                                    acc[i][j], 68, wmma::mem_row_major);
    __syncthreads();

#pragma unroll
    for (int it = 0; it < 16; it++) {
        int e = it * 256 + tid;          // half2 index: 128 rows x 32 half2
        int r = e >> 5, c2 = e & 31;
        float lo = s_x[r * 68 + c2 * 2];
        float hi = s_x[r * 68 + c2 * 2 + 1];
        *(__half2*)(Y + (row0 + r) * KQ_ + c2 * 2) =
            __floats2half2_rn(lo, hi);
    }
}

// ---------------------------------------------------------------------------
// K2: fused streaming attention, fp16 datapath (fp32 accumulate).
// Block = 128 b-rows x one n. 512 threads, L-chunk 128.
// Per chunk: QK mma fp16 (warp 32x32, 4 accs) -> exp -> E (fp16) to smem +
// unnormalized attn write + reg rowsums -> PV mma fp16 (warp 32x16, 2 persist).
// ---------------------------------------------------------------------------
#define QLDS 72    // halves
#define KLDS 72
#define ELDS 136
#define SQ_OFF 0
#define SK_OFF (128 * QLDS)                 //  9216 halves
#define SV_OFF (SK_OFF + 128 * KLDS)        // 18432
#define SE_OFF (SV_OFF + 128 * KLDS)        // 27648
#define SE_HALVES (128 * ELDS)              // 17408
#define SI_OFF (SE_OFF + SE_HALVES)         // 45056 (halves; 8B aligned)
#define ATTN_SMEM ((SI_OFF) * 2 + 128 * 4)  // 90,624 B

__global__ __launch_bounds__(512)
void attn_kernel(float* __restrict__ out)
{
    extern __shared__ __half hsm[];
    __half* s_q   = hsm + SQ_OFF;   // [128][QLDS] q tile
    __half* s_k   = hsm + SK_OFF;   // [128][KLDS] kb chunk
    __half* s_v   = hsm + SV_OFF;   // [128][KLDS] vb chunk
    __half* s_e   = hsm + SE_OFF;   // [128][ELDS] E chunk (fp16)
    float*  s_inv = (float*)(hsm + SI_OFF);  // [128] 1/rowsum

    const int n   = blockIdx.y;
    const int b0  = blockIdx.x * 128;
    const int tid = threadIdx.x;
    const int w    = tid >> 5;
    const int lane = tid & 31;

    const __half* kb = g_kbuf + (size_t)n * L_ * KQ_;
    const __half* vb = g_vbuf + (size_t)n * L_ * OUT_;
    float* attn_out = out + RESULT_ELEMS + ((size_t)n * B_ + b0) * L_;

    // Prologue: stage q tile + kb chunk 0 (each 128x64 halves = 1024 x 16B).
#pragma unroll
    for (int i = 0; i < 2; i++) {
        int e = i * 512 + tid;
        int r = e >> 3, c8 = e & 7;
        cp_async16(s_q + r * QLDS + c8 * 8, g_q + (size_t)(b0 + r) * KQ_ + c8 * 8);
        cp_async16(s_k + r * KLDS + c8 * 8, kb + (size_t)r * KQ_ + c8 * 8);
    }
    cp_commit();

    const int ewr = w >> 2;   // 0..3
    const int ewc = w & 3;    // 0..3

    wmma::fragment<wmma::accumulator, 16, 16, 16, float> pacc[2];
#pragma unroll
    for (int i = 0; i < 2; i++) wmma::fill_fragment(pacc[i], 0.0f);

    float rs[8];
#pragma unroll
    for (int i = 0; i < 8; i++) rs[i] = 0.f;

#pragma unroll 1
    for (int c = 0; c < 8; c++) {
        const int l0 = c * 128;

        // issue vb_c into s_v (overlaps QK mma)
#pragma unroll
        for (int i = 0; i < 2; i++) {
            int e = i * 512 + tid;
            int r = e >> 3, c8 = e & 7;
            cp_async16(s_v + r * KLDS + c8 * 8,
                       vb + (size_t)(l0 + r) * OUT_ + c8 * 8);
        }
        cp_commit();
        cp_wait1();          // kb_c (and q on first iter) arrived
        __syncthreads();

        // ---- QK mma fp16: E tile 32x32 per warp, 4 k-steps of 16 ----
        wmma::fragment<wmma::accumulator, 16, 16, 16, float> eacc[2][2];
#pragma unroll
        for (int i = 0; i < 2; i++)
#pragma unroll
            for (int j = 0; j < 2; j++)
                wmma::fill_fragment(eacc[i][j], 0.0f);

#pragma unroll
        for (int ks = 0; ks < 4; ks++) {
            const int k = ks * 16;
            wmma::fragment<wmma::matrix_a, 16, 16, 16, __half, wmma::row_major> a[2];
            wmma::fragment<wmma::matrix_b, 16, 16, 16, __half, wmma::col_major> b[2];
#pragma unroll
            for (int i = 0; i < 2; i++)
                wmma::load_matrix_sync(a[i], s_q + (ewr * 32 + i * 16) * QLDS + k, QLDS);
#pragma unroll
            for (int j = 0; j < 2; j++)
                wmma::load_matrix_sync(b[j], s_k + (ewc * 32 + j * 16) * KLDS + k, KLDS);
#pragma unroll
            for (int i = 0; i < 2; i++)
#pragma unroll
                for (int j = 0; j < 2; j++)
                    wmma::mma_sync(eacc[i][j], a[i], b[j], eacc[i][j]);
        }

        // exp -> fp16, park in s_e (elementwise fp32->fp16 acc frag convert)
#pragma unroll
        for (int i = 0; i < 2; i++)
#pragma unroll
            for (int j = 0; j < 2; j++) {
                wmma::fragment<wmma::accumulator, 16, 16, 16, __half> eh;
#pragma unroll
                for (int t = 0; t < eacc[i][j].num_elements; t++)
                    eh.x[t] = __float2half(__expf(eacc[i][j].x[t] * 0.125f));
                wmma::store_matrix_sync(
                    s_e + (ewr * 32 + i * 16) * ELDS + ewc * 32 + j * 16,
                    eh, ELDS, wmma::mem_row_major);
            }
        __syncthreads();     // s_e ready; s_k free

        // issue kb_{c+1} into s_k (overlaps rowsum + PV mma)
        if (c < 7) {
            const __half* src = kb + (size_t)(l0 + 128) * KQ_;
#pragma unroll
            for (int i = 0; i < 2; i++) {
                int e = i * 512 + tid;
                int r = e >> 3, c8 = e & 7;
                cp_async16(s_k + r * KLDS + c8 * 8, src + (size_t)r * KQ_ + c8 * 8);
            }
            cp_commit();
        }

        // ---- rowsums + unnormalized attn write (warp w owns rows w*8..w*8+7)
#pragma unroll
        for (int i = 0; i < 8; i++) {
            const int r = w * 8 + i;
            const __half2* hrow = (const __half2*)(s_e + r * ELDS);
            float* arow = attn_out + (size_t)r * L_ + l0;
            float2 p0 = __half22float2(hrow[lane]);        // cols 2l, 2l+1
            float2 p1 = __half22float2(hrow[32 + lane]);   // cols 64+2l, 64+2l+1
            rs[i] += (p0.x + p0.y) + (p1.x + p1.y);
            *(float2*)(arow + 2 * lane)      = p0;
            *(float2*)(arow + 64 + 2 * lane) = p1;
        }

        if (c < 7) cp_wait1(); else cp_wait0();   // vb_c arrived
        __syncthreads();

        // ---- PV mma fp16: result tile 32x16 per warp, 8 k-steps of 16 ----
#pragma unroll
        for (int ks = 0; ks < 8; ks++) {
            const int k = ks * 16;
            wmma::fragment<wmma::matrix_a, 16, 16, 16, __half, wmma::row_major> a[2];
            wmma::fragment<wmma::matrix_b, 16, 16, 16, __half, wmma::row_major> b;
#pragma unroll
            for (int i = 0; i < 2; i++)
                wmma::load_matrix_sync(a[i], s_e + (ewr * 32 + i * 16) * ELDS + k, ELDS);
            wmma::load_matrix_sync(b, s_v + k * KLDS + ewc * 16, KLDS);
#pragma unroll
            for (int i = 0; i < 2; i++)
                wmma::mma_sync(pacc[i], a[i], b, pacc[i]);
        }
        __syncthreads();     // s_e / s_v free for next chunk
    }

    // ---- epilogue: rowsum reduce ----
#pragma unroll
    for (int i = 0; i < 8; i++) {
        float s = rs[i];
#pragma unroll
        for (int off = 16; off; off >>= 1)
            s += __shfl_xor_sync(0xffffffffu, s, off);
        if (lane == 0) s_inv[w * 8 + i] = 1.0f / s;
    }
    // park PV accumulators as float [128][68] in the s_e region (34,816 B fits)
    float* s_red = (float*)s_e;
#pragma unroll
    for (int i = 0; i < 2; i++)
        wmma::store_matrix_sync(s_red + (ewr * 32 + i * 16) * 68 + ewc * 16,
                                pacc[i], 68, wmma::mem_row_major);
    __syncthreads();

    // scaled result write: out[(b0+r)*N*64 + n*64 + c]
#pragma unroll
    for (int it = 0; it < 4; it++) {
        int e = it * 512 + tid;
        int r = e >> 4, c4 = e & 15;
        const float inv = s_inv[r];
        float4 v = *(float4*)(s_red + r * 68 + c4 * 4);
        v.x *= inv; v.y *= inv; v.z *= inv; v.w *= inv;
        *(float4*)(out + ((size_t)(b0 + r) * N_ + n) * OUT_ + c4 * 4) = v;
    }

    // in-place attn normalization (128 x 1024 RMW, coalesced)
#pragma unroll 1
    for (int it = 0; it < 64; it++) {
        int e = it * 512 + tid;
        int r = e >> 8, c4 = e & 255;
        const float inv = s_inv[r];
        float4* p = (float4*)(attn_out + (size_t)r * L_ + c4 * 4);
        float4 v = *p;
        v.x *= inv; v.y *= inv; v.z *= inv; v.w *= inv;
        *p = v;
    }
}

// ---------------------------------------------------------------------------
extern "C" void kernel_launch(void* const* d_in, const int* in_sizes, int n_in,
                              void* d_out, int out_size)
{
    const float* queries = (const float*)d_in[0];
    const float* keys    = (const float*)d_in[1];
    const float* values  = (const float*)d_in[2];
    const float* Wq      = (const float*)d_in[3];
    const float* Wk      = (const float*)d_in[4];
    const float* Wv      = (const float*)d_in[5];
    float* out = (float*)d_out;

    cudaFuncSetAttribute(attn_kernel,
                         cudaFuncAttributeMaxDynamicSharedMemorySize, ATTN_SMEM);
    cudaFuncSetAttribute(proj_tf32_kernel,
                         cudaFuncAttributeMaxDynamicSharedMemorySize, PROJ_SMEM);

    __half *kbuf_ptr, *vbuf_ptr;
    cudaGetSymbolAddress((void**)&kbuf_ptr, g_kbuf);
    cudaGetSymbolAddress((void**)&vbuf_ptr, g_vbuf);

    // K1: combined key/value projections + fused q projection (fp16 outputs)
    dim3 pgrid((N_ * L_) / 128, 2);   // (2048, 2)
    proj_tf32_kernel<<<pgrid, 256, PROJ_SMEM>>>(queries, keys, values,
                                                Wq, Wk, Wv, kbuf_ptr, vbuf_ptr);

    // K2: fused attention (fp16 datapath)
    dim3 grid(B_ / 128, N_);   // (2, 256)
    attn_kernel<<<grid, 512, ATTN_SMEM>>>(out);
}

// round 11
// speedup vs baseline: 3.1785x; 1.3451x over previous
#include <cuda_runtime.h>
#include <cuda_fp16.h>
#include <cuda_bf16.h>
#include <cstdint>
#include <mma.h>

using namespace nvcuda;

// Problem constants
#define B_  256
#define N_  256
#define L_  1024
#define D_  256
#define KQ_ 64
#define OUT_ 64

#define RESULT_ELEMS (B_ * N_ * OUT_)   // 4,194,304

// Scratch (device globals: allocation-free per harness rules) — fp16
__device__ __half g_q[B_ * KQ_];
__device__ __half g_kbuf[(size_t)N_ * L_ * KQ_];  // 33.5 MB
__device__ __half g_vbuf[(size_t)N_ * L_ * OUT_]; // 33.5 MB

// ---------------------------------------------------------------------------
// cp.async helpers (16B)
// ---------------------------------------------------------------------------
__device__ __forceinline__ void cp_async16(void* smem_dst, const void* gsrc)
{
    unsigned int s = (unsigned int)__cvta_generic_to_shared(smem_dst);
    asm volatile("cp.async.ca.shared.global [%0], [%1], 16;\n" :: "r"(s), "l"(gsrc));
}
__device__ __forceinline__ void cp_commit()
{
    asm volatile("cp.async.commit_group;\n");
}
__device__ __forceinline__ void cp_wait1()
{
    asm volatile("cp.async.wait_group 1;\n");
}
__device__ __forceinline__ void cp_wait0()
{
    asm volatile("cp.async.wait_group 0;\n");
}

// ---------------------------------------------------------------------------
// K1: combined K/V projection, fp16 datapath (fp32 accumulate) + fused qproj.
// blockIdx.y: 0 -> keys@Wk, 1 -> values@Wv. Outputs fp16.
// Block: 128 rows x 64 cols, 256 threads. X chunks (128x32) through a
// register software pipeline (LDG c+1 overlaps mma c). 3 CTAs/SM.
// ---------------------------------------------------------------------------
#define PWLD 72    // halves; 144B stride -> 4-bank shift, conflict-free LDSM
#define PXLD 40    // halves;  80B stride -> 20-bank shift, tiles all 32 banks
#define PXSTG (128 * PXLD)
#define PROJ_SMEM ((D_ * PWLD + 2 * PXSTG) * 2)   // 57,344 B

__global__ __launch_bounds__(256, 3)
void proj_fp16_kernel(const float* __restrict__ queries,
                      const float* __restrict__ keys,
                      const float* __restrict__ values,
                      const float* __restrict__ Wq,
                      const float* __restrict__ Wk,
                      const float* __restrict__ Wv,
                      __half* __restrict__ kbuf,
                      __half* __restrict__ vbuf)
{
    const int tid = threadIdx.x;

    // ---- fused q projection (16 blocks of y==0, 1024 outputs each) ----
    if (blockIdx.y == 0 && blockIdx.x < 16) {
        const int base = blockIdx.x * 1024;
#pragma unroll
        for (int i = 0; i < 4; i++) {
            int o = base + i * 256 + tid;
            int b = o >> 6, j = o & 63;
            float acc = 0.f;
            const float* qrow = queries + b * D_;
            const float* wcol = Wq + j;
#pragma unroll 8
            for (int d = 0; d < D_; d++)
                acc += qrow[d] * wcol[(size_t)d * KQ_];
            g_q[o] = __float2half(acc);
        }
    }

    const float* X = (blockIdx.y == 0) ? keys : values;
    const float* W = (blockIdx.y == 0) ? Wk : Wv;
    __half*      Y = (blockIdx.y == 0) ? kbuf : vbuf;

    extern __shared__ __half psm[];
    __half* s_w = psm;               // [256][PWLD]
    __half* s_x = psm + D_ * PWLD;   // [2][128][PXLD]

    const int w  = tid >> 5;
    const int wr = w >> 1;   // 0..3
    const int wc = w & 1;    // 0..1
    const size_t row0 = (size_t)blockIdx.x * 128;

    // Stage all of W (256x64) as fp16. 4096 float4s, 16 per thread.
#pragma unroll
    for (int i = 0; i < 16; i++) {
        int f = i * 256 + tid;
        int r = f >> 4, c4 = f & 15;
        float4 v = *(const float4*)(W + (size_t)r * KQ_ + c4 * 4);
        __half2 h0 = __floats2half2_rn(v.x, v.y);
        __half2 h1 = __floats2half2_rn(v.z, v.w);
        *(uint2*)(s_w + r * PWLD + c4 * 4) = make_uint2(
            *(unsigned int*)&h0, *(unsigned int*)&h1);
    }

    // Register software pipeline over 8 chunks of 32 K-columns.
    const int xr = tid >> 1;          // row 0..127
    const int xh = tid & 1;           // half-chunk (16 cols)
    const float* xrow = X + (row0 + xr) * D_ + xh * 16;

    float4 rx[4];
#pragma unroll
    for (int i = 0; i < 4; i++)
        rx[i] = *(const float4*)(xrow + i * 4);   // chunk 0

    wmma::fragment<wmma::accumulator, 16, 16, 16, float> acc[2][2];
#pragma unroll
    for (int i = 0; i < 2; i++)
#pragma unroll
        for (int j = 0; j < 2; j++)
            wmma::fill_fragment(acc[i][j], 0.0f);

#pragma unroll 1
    for (int c = 0; c < 8; c++) {
        // STS chunk c (convert fp32 regs -> fp16 smem)
        __half* xb = s_x + (c & 1) * PXSTG;
#pragma unroll
        for (int i = 0; i < 4; i++) {
            __half2 h0 = __floats2half2_rn(rx[i].x, rx[i].y);
            __half2 h1 = __floats2half2_rn(rx[i].z, rx[i].w);
            *(uint2*)(xb + xr * PXLD + xh * 16 + i * 4) = make_uint2(
                *(unsigned int*)&h0, *(unsigned int*)&h1);
        }
        __syncthreads();

        // issue LDGs for chunk c+1 (latency overlaps the mma below)
        if (c < 7) {
#pragma unroll
            for (int i = 0; i < 4; i++)
                rx[i] = *(const float4*)(xrow + (c + 1) * 32 + i * 4);
        }

        // mma fp16: 2 k-steps of 16
        const int k0 = c * 32;
#pragma unroll
        for (int ks = 0; ks < 2; ks++) {
            const int k = ks * 16;
            wmma::fragment<wmma::matrix_a, 16, 16, 16, __half, wmma::row_major> a[2];
            wmma::fragment<wmma::matrix_b, 16, 16, 16, __half, wmma::row_major> b[2];
#pragma unroll
            for (int i = 0; i < 2; i++)
                wmma::load_matrix_sync(a[i], xb + (wr * 32 + i * 16) * PXLD + k, PXLD);
#pragma unroll
            for (int j = 0; j < 2; j++)
                wmma::load_matrix_sync(b[j], s_w + (k0 + k) * PWLD + wc * 32 + j * 16, PWLD);
#pragma unroll
            for (int i = 0; i < 2; i++)
#pragma unroll
                for (int j = 0; j < 2; j++)
                    wmma::mma_sync(acc[i][j], a[i], b[j], acc[i][j]);
        }
        __syncthreads();
    }

    // Epilogue: fp32 acc -> fp16 fragment -> direct global store (ld = 64)
#pragma unroll
    for (int i = 0; i < 2; i++)
#pragma unroll
        for (int j = 0; j < 2; j++) {
            wmma::fragment<wmma::accumulator, 16, 16, 16, __half> h;
#pragma unroll
            for (int t = 0; t < acc[i][j].num_elements; t++)
                h.x[t] = __float2half(acc[i][j].x[t]);
            wmma::store_matrix_sync(Y + (row0 + wr * 32 + i * 16) * KQ_ + wc * 32 + j * 16,
                                    h, KQ_, wmma::mem_row_major);
        }
}

// ---------------------------------------------------------------------------
// K2: fused streaming attention, fp16 datapath (proven R9 config, unchanged).
// ---------------------------------------------------------------------------
#define QLDS 72    // halves
#define KLDS 72
#define ELDS 136
#define SQ_OFF 0
#define SK_OFF (128 * QLDS)                 //  9216 halves
#define SV_OFF (SK_OFF + 128 * KLDS)        // 18432
#define SE_OFF (SV_OFF + 128 * KLDS)        // 27648
#define SE_HALVES (128 * ELDS)              // 17408
#define SI_OFF (SE_OFF + SE_HALVES)         // 45056 (halves; 8B aligned)
#define ATTN_SMEM ((SI_OFF) * 2 + 128 * 4)  // 90,624 B

__global__ __launch_bounds__(512)
void attn_kernel(float* __restrict__ out)
{
    extern __shared__ __half hsm[];
    __half* s_q   = hsm + SQ_OFF;   // [128][QLDS] q tile
    __half* s_k   = hsm + SK_OFF;   // [128][KLDS] kb chunk
    __half* s_v   = hsm + SV_OFF;   // [128][KLDS] vb chunk
    __half* s_e   = hsm + SE_OFF;   // [128][ELDS] E chunk (fp16)
    float*  s_inv = (float*)(hsm + SI_OFF);  // [128] 1/rowsum

    const int n   = blockIdx.y;
    const int b0  = blockIdx.x * 128;
    const int tid = threadIdx.x;
    const int w    = tid >> 5;
    const int lane = tid & 31;

    const __half* kb = g_kbuf + (size_t)n * L_ * KQ_;
    const __half* vb = g_vbuf + (size_t)n * L_ * OUT_;
    float* attn_out = out + RESULT_ELEMS + ((size_t)n * B_ + b0) * L_;

    // Prologue: stage q tile + kb chunk 0 (each 128x64 halves = 1024 x 16B).
#pragma unroll
    for (int i = 0; i < 2; i++) {
        int e = i * 512 + tid;
        int r = e >> 3, c8 = e & 7;
        cp_async16(s_q + r * QLDS + c8 * 8, g_q + (size_t)(b0 + r) * KQ_ + c8 * 8);
        cp_async16(s_k + r * KLDS + c8 * 8, kb + (size_t)r * KQ_ + c8 * 8);
    }
    cp_commit();

    const int ewr = w >> 2;   // 0..3
    const int ewc = w & 3;    // 0..3

    wmma::fragment<wmma::accumulator, 16, 16, 16, float> pacc[2];
#pragma unroll
    for (int i = 0; i < 2; i++) wmma::fill_fragment(pacc[i], 0.0f);

    float rs[8];
#pragma unroll
    for (int i = 0; i < 8; i++) rs[i] = 0.f;

#pragma unroll 1
    for (int c = 0; c < 8; c++) {
        const int l0 = c * 128;

        // issue vb_c into s_v (overlaps QK mma)
#pragma unroll
        for (int i = 0; i < 2; i++) {
            int e = i * 512 + tid;
            int r = e >> 3, c8 = e & 7;
            cp_async16(s_v + r * KLDS + c8 * 8,
                       vb + (size_t)(l0 + r) * OUT_ + c8 * 8);
        }
        cp_commit();
        cp_wait1();          // kb_c (and q on first iter) arrived
        __syncthreads();

        // ---- QK mma fp16: E tile 32x32 per warp, 4 k-steps of 16 ----
        wmma::fragment<wmma::accumulator, 16, 16, 16, float> eacc[2][2];
#pragma unroll
        for (int i = 0; i < 2; i++)
#pragma unroll
            for (int j = 0; j < 2; j++)
                wmma::fill_fragment(eacc[i][j], 0.0f);

#pragma unroll
        for (int ks = 0; ks < 4; ks++) {
            const int k = ks * 16;
            wmma::fragment<wmma::matrix_a, 16, 16, 16, __half, wmma::row_major> a[2];
            wmma::fragment<wmma::matrix_b, 16, 16, 16, __half, wmma::col_major> b[2];
#pragma unroll
            for (int i = 0; i < 2; i++)
                wmma::load_matrix_sync(a[i], s_q + (ewr * 32 + i * 16) * QLDS + k, QLDS);
#pragma unroll
            for (int j = 0; j < 2; j++)
                wmma::load_matrix_sync(b[j], s_k + (ewc * 32 + j * 16) * KLDS + k, KLDS);
#pragma unroll
            for (int i = 0; i < 2; i++)
#pragma unroll
                for (int j = 0; j < 2; j++)
                    wmma::mma_sync(eacc[i][j], a[i], b[j], eacc[i][j]);
        }

        // exp -> fp16, park in s_e
#pragma unroll
        for (int i = 0; i < 2; i++)
#pragma unroll
            for (int j = 0; j < 2; j++) {
                wmma::fragment<wmma::accumulator, 16, 16, 16, __half> eh;
#pragma unroll
                for (int t = 0; t < eacc[i][j].num_elements; t++)
                    eh.x[t] = __float2half(__expf(eacc[i][j].x[t] * 0.125f));
                wmma::store_matrix_sync(
                    s_e + (ewr * 32 + i * 16) * ELDS + ewc * 32 + j * 16,
                    eh, ELDS, wmma::mem_row_major);
            }
        __syncthreads();     // s_e ready; s_k free

        // issue kb_{c+1} into s_k (overlaps rowsum + PV mma)
        if (c < 7) {
            const __half* src = kb + (size_t)(l0 + 128) * KQ_;
#pragma unroll
            for (int i = 0; i < 2; i++) {
                int e = i * 512 + tid;
                int r = e >> 3, c8 = e & 7;
                cp_async16(s_k + r * KLDS + c8 * 8, src + (size_t)r * KQ_ + c8 * 8);
            }
            cp_commit();
        }

        // ---- rowsums + unnormalized attn write (warp w owns rows w*8..w*8+7)
#pragma unroll
        for (int i = 0; i < 8; i++) {
            const int r = w * 8 + i;
            const __half2* hrow = (const __half2*)(s_e + r * ELDS);
            float* arow = attn_out + (size_t)r * L_ + l0;
            float2 p0 = __half22float2(hrow[lane]);
            float2 p1 = __half22float2(hrow[32 + lane]);
            rs[i] += (p0.x + p0.y) + (p1.x + p1.y);
            *(float2*)(arow + 2 * lane)      = p0;
            *(float2*)(arow + 64 + 2 * lane) = p1;
        }

        if (c < 7) cp_wait1(); else cp_wait0();   // vb_c arrived
        __syncthreads();

        // ---- PV mma fp16: result tile 32x16 per warp, 8 k-steps of 16 ----
#pragma unroll
        for (int ks = 0; ks < 8; ks++) {
            const int k = ks * 16;
            wmma::fragment<wmma::matrix_a, 16, 16, 16, __half, wmma::row_major> a[2];
            wmma::fragment<wmma::matrix_b, 16, 16, 16, __half, wmma::row_major> b;
#pragma unroll
            for (int i = 0; i < 2; i++)
                wmma::load_matrix_sync(a[i], s_e + (ewr * 32 + i * 16) * ELDS + k, ELDS);
            wmma::load_matrix_sync(b, s_v + k * KLDS + ewc * 16, KLDS);
#pragma unroll
            for (int i = 0; i < 2; i++)
                wmma::mma_sync(pacc[i], a[i], b, pacc[i]);
        }
        __syncthreads();     // s_e / s_v free for next chunk
    }

    // ---- epilogue: rowsum reduce ----
#pragma unroll
    for (int i = 0; i < 8; i++) {
        float s = rs[i];
#pragma unroll
        for (int off = 16; off; off >>= 1)
            s += __shfl_xor_sync(0xffffffffu, s, off);
        if (lane == 0) s_inv[w * 8 + i] = 1.0f / s;
    }
    // park PV accumulators as float [128][68] in the s_e region
    float* s_red = (float*)s_e;
#pragma unroll
    for (int i = 0; i < 2; i++)
        wmma::store_matrix_sync(s_red + (ewr * 32 + i * 16) * 68 + ewc * 16,
                                pacc[i], 68, wmma::mem_row_major);
    __syncthreads();

    // scaled result write: out[(b0+r)*N*64 + n*64 + c]
#pragma unroll
    for (int it = 0; it < 4; it++) {
        int e = it * 512 + tid;
        int r = e >> 4, c4 = e & 15;
        const float inv = s_inv[r];
        float4 v = *(float4*)(s_red + r * 68 + c4 * 4);
        v.x *= inv; v.y *= inv; v.z *= inv; v.w *= inv;
        *(float4*)(out + ((size_t)(b0 + r) * N_ + n) * OUT_ + c4 * 4) = v;
    }

    // in-place attn normalization (128 x 1024 RMW, coalesced)
#pragma unroll 1
    for (int it = 0; it < 64; it++) {
        int e = it * 512 + tid;
        int r = e >> 8, c4 = e & 255;
        const float inv = s_inv[r];
        float4* p = (float4*)(attn_out + (size_t)r * L_ + c4 * 4);
        float4 v = *p;
        v.x *= inv; v.y *= inv; v.z *= inv; v.w *= inv;
        *p = v;
    }
}

// ---------------------------------------------------------------------------
extern "C" void kernel_launch(void* const* d_in, const int* in_sizes, int n_in,
                              void* d_out, int out_size)
{
    const float* queries = (const float*)d_in[0];
    const float* keys    = (const float*)d_in[1];
    const float* values  = (const float*)d_in[2];
    const float* Wq      = (const float*)d_in[3];
    const float* Wk      = (const float*)d_in[4];
    const float* Wv      = (const float*)d_in[5];
    float* out = (float*)d_out;

    cudaFuncSetAttribute(attn_kernel,
                         cudaFuncAttributeMaxDynamicSharedMemorySize, ATTN_SMEM);
    cudaFuncSetAttribute(proj_fp16_kernel,
                         cudaFuncAttributeMaxDynamicSharedMemorySize, PROJ_SMEM);

    __half *kbuf_ptr, *vbuf_ptr;
    cudaGetSymbolAddress((void**)&kbuf_ptr, g_kbuf);
    cudaGetSymbolAddress((void**)&vbuf_ptr, g_vbuf);

    // K1: combined key/value projections + fused q projection (fp16)
    dim3 pgrid((N_ * L_) / 128, 2);   // (2048, 2)
    proj_fp16_kernel<<<pgrid, 256, PROJ_SMEM>>>(queries, keys, values,
                                                Wq, Wk, Wv, kbuf_ptr, vbuf_ptr);

    // K2: fused attention (fp16 datapath)
    dim3 grid(B_ / 128, N_);   // (2, 256)
    attn_kernel<<<grid, 512, ATTN_SMEM>>>(out);
}

// round 15
// speedup vs baseline: 3.2022x; 1.0075x over previous
#include <cuda_runtime.h>
#include <cuda_fp16.h>
#include <cuda_bf16.h>
#include <cstdint>
#include <mma.h>

using namespace nvcuda;

// Problem constants
#define B_  256
#define N_  256
#define L_  1024
#define D_  256
#define KQ_ 64
#define OUT_ 64

#define RESULT_ELEMS (B_ * N_ * OUT_)   // 4,194,304

// Scratch (device globals: allocation-free per harness rules) — fp16
__device__ __half g_q[B_ * KQ_];
__device__ __half g_kbuf[(size_t)N_ * L_ * KQ_];  // 33.5 MB
__device__ __half g_vbuf[(size_t)N_ * L_ * OUT_]; // 33.5 MB

// ---------------------------------------------------------------------------
// cp.async helpers (16B)
// ---------------------------------------------------------------------------
__device__ __forceinline__ void cp_async16(void* smem_dst, const void* gsrc)
{
    unsigned int s = (unsigned int)__cvta_generic_to_shared(smem_dst);
    asm volatile("cp.async.ca.shared.global [%0], [%1], 16;\n" :: "r"(s), "l"(gsrc));
}
__device__ __forceinline__ void cp_commit()
{
    asm volatile("cp.async.commit_group;\n");
}
__device__ __forceinline__ void cp_wait1()
{
    asm volatile("cp.async.wait_group 1;\n");
}
__device__ __forceinline__ void cp_wait0()
{
    asm volatile("cp.async.wait_group 0;\n");
}

// ---------------------------------------------------------------------------
// K1: combined K/V projection, fp16 datapath (fp32 accumulate) + fused qproj.
// (unchanged from R11 — measured ~146 us)
// ---------------------------------------------------------------------------
#define PWLD 72
#define PXLD 40
#define PXSTG (128 * PXLD)
#define PROJ_SMEM ((D_ * PWLD + 2 * PXSTG) * 2)   // 57,344 B

__global__ __launch_bounds__(256, 3)
void proj_fp16_kernel(const float* __restrict__ queries,
                      const float* __restrict__ keys,
                      const float* __restrict__ values,
                      const float* __restrict__ Wq,
                      const float* __restrict__ Wk,
                      const float* __restrict__ Wv,
                      __half* __restrict__ kbuf,
                      __half* __restrict__ vbuf)
{
    const int tid = threadIdx.x;

    // ---- fused q projection (16 blocks of y==0, 1024 outputs each) ----
    if (blockIdx.y == 0 && blockIdx.x < 16) {
        const int base = blockIdx.x * 1024;
#pragma unroll
        for (int i = 0; i < 4; i++) {
            int o = base + i * 256 + tid;
            int b = o >> 6, j = o & 63;
            float acc = 0.f;
            const float* qrow = queries + b * D_;
            const float* wcol = Wq + j;
#pragma unroll 8
            for (int d = 0; d < D_; d++)
                acc += qrow[d] * wcol[(size_t)d * KQ_];
            g_q[o] = __float2half(acc);
        }
    }

    const float* X = (blockIdx.y == 0) ? keys : values;
    const float* W = (blockIdx.y == 0) ? Wk : Wv;
    __half*      Y = (blockIdx.y == 0) ? kbuf : vbuf;

    extern __shared__ __half psm[];
    __half* s_w = psm;               // [256][PWLD]
    __half* s_x = psm + D_ * PWLD;   // [2][128][PXLD]

    const int w  = tid >> 5;
    const int wr = w >> 1;   // 0..3
    const int wc = w & 1;    // 0..1
    const size_t row0 = (size_t)blockIdx.x * 128;

    // Stage all of W (256x64) as fp16.
#pragma unroll
    for (int i = 0; i < 16; i++) {
        int f = i * 256 + tid;
        int r = f >> 4, c4 = f & 15;
        float4 v = *(const float4*)(W + (size_t)r * KQ_ + c4 * 4);
        __half2 h0 = __floats2half2_rn(v.x, v.y);
        __half2 h1 = __floats2half2_rn(v.z, v.w);
        *(uint2*)(s_w + r * PWLD + c4 * 4) = make_uint2(
            *(unsigned int*)&h0, *(unsigned int*)&h1);
    }

    const int xr = tid >> 1;
    const int xh = tid & 1;
    const float* xrow = X + (row0 + xr) * D_ + xh * 16;

    float4 rx[4];
#pragma unroll
    for (int i = 0; i < 4; i++)
        rx[i] = *(const float4*)(xrow + i * 4);   // chunk 0

    wmma::fragment<wmma::accumulator, 16, 16, 16, float> acc[2][2];
#pragma unroll
    for (int i = 0; i < 2; i++)
#pragma unroll
        for (int j = 0; j < 2; j++)
            wmma::fill_fragment(acc[i][j], 0.0f);

#pragma unroll 1
    for (int c = 0; c < 8; c++) {
        __half* xb = s_x + (c & 1) * PXSTG;
#pragma unroll
        for (int i = 0; i < 4; i++) {
            __half2 h0 = __floats2half2_rn(rx[i].x, rx[i].y);
            __half2 h1 = __floats2half2_rn(rx[i].z, rx[i].w);
            *(uint2*)(xb + xr * PXLD + xh * 16 + i * 4) = make_uint2(
                *(unsigned int*)&h0, *(unsigned int*)&h1);
        }
        __syncthreads();

        if (c < 7) {
#pragma unroll
            for (int i = 0; i < 4; i++)
                rx[i] = *(const float4*)(xrow + (c + 1) * 32 + i * 4);
        }

        const int k0 = c * 32;
#pragma unroll
        for (int ks = 0; ks < 2; ks++) {
            const int k = ks * 16;
            wmma::fragment<wmma::matrix_a, 16, 16, 16, __half, wmma::row_major> a[2];
            wmma::fragment<wmma::matrix_b, 16, 16, 16, __half, wmma::row_major> b[2];
#pragma unroll
            for (int i = 0; i < 2; i++)
                wmma::load_matrix_sync(a[i], xb + (wr * 32 + i * 16) * PXLD + k, PXLD);
#pragma unroll
            for (int j = 0; j < 2; j++)
                wmma::load_matrix_sync(b[j], s_w + (k0 + k) * PWLD + wc * 32 + j * 16, PWLD);
#pragma unroll
            for (int i = 0; i < 2; i++)
#pragma unroll
                for (int j = 0; j < 2; j++)
                    wmma::mma_sync(acc[i][j], a[i], b[j], acc[i][j]);
        }
        __syncthreads();
    }

#pragma unroll
    for (int i = 0; i < 2; i++)
#pragma unroll
        for (int j = 0; j < 2; j++) {
            wmma::fragment<wmma::accumulator, 16, 16, 16, __half> h;
#pragma unroll
            for (int t = 0; t < acc[i][j].num_elements; t++)
                h.x[t] = __float2half(acc[i][j].x[t]);
            wmma::store_matrix_sync(Y + (row0 + wr * 32 + i * 16) * KQ_ + wc * 32 + j * 16,
                                    h, KQ_, wmma::mem_row_major);
        }
}

// ---------------------------------------------------------------------------
// K2: fused streaming attention, fp16. Block = 64 b-rows x one n.
// 256 threads (8 warps), 2 CTAs/SM (RF: 2x256x128 = 64K regs exactly).
// Same per-warp tiles as the proven config: QK 32x32 (4 accs), PV 32x16.
// ---------------------------------------------------------------------------
#define QLDS 72    // halves
#define KLDS 72
#define ELDS 136
#define SQ_OFF 0
#define SK_OFF (64 * QLDS)                  //  4608 halves
#define SV_OFF (SK_OFF + 128 * KLDS)        // 13824
#define SE_OFF (SV_OFF + 128 * KLDS)        // 23040
#define SE_HALVES (64 * ELDS)               //  8704
#define SI_OFF (SE_OFF + SE_HALVES)         // 31744 halves (8B aligned)
#define ATTN_SMEM ((SI_OFF) * 2 + 64 * 4)   // 63,744 B

__global__ __launch_bounds__(256, 2)
void attn_kernel(float* __restrict__ out)
{
    extern __shared__ __half hsm[];
    __half* s_q   = hsm + SQ_OFF;   // [64][QLDS] q tile
    __half* s_k   = hsm + SK_OFF;   // [128][KLDS] kb chunk
    __half* s_v   = hsm + SV_OFF;   // [128][KLDS] vb chunk
    __half* s_e   = hsm + SE_OFF;   // [64][ELDS] E chunk (fp16)
    float*  s_inv = (float*)(hsm + SI_OFF);  // [64] 1/rowsum

    const int n   = blockIdx.y;
    const int b0  = blockIdx.x * 64;
    const int tid = threadIdx.x;
    const int w    = tid >> 5;      // 0..7
    const int lane = tid & 31;

    const __half* kb = g_kbuf + (size_t)n * L_ * KQ_;
    const __half* vb = g_vbuf + (size_t)n * L_ * OUT_;
    float* attn_out = out + RESULT_ELEMS + ((size_t)n * B_ + b0) * L_;

    // Prologue: stage q tile (64x64: 512 x 16B) + kb chunk 0 (128x64: 1024 x 16B)
#pragma unroll
    for (int i = 0; i < 2; i++) {
        int e = i * 256 + tid;
        int r = e >> 3, c8 = e & 7;
        cp_async16(s_q + r * QLDS + c8 * 8, g_q + (size_t)(b0 + r) * KQ_ + c8 * 8);
    }
#pragma unroll
    for (int i = 0; i < 4; i++) {
        int e = i * 256 + tid;
        int r = e >> 3, c8 = e & 7;
        cp_async16(s_k + r * KLDS + c8 * 8, kb + (size_t)r * KQ_ + c8 * 8);
    }
    cp_commit();

    const int ewr = w >> 2;   // 0..1 (32-row band of the 64-row tile)
    const int ewc = w & 3;    // 0..3 (32-col band for QK; 16-col for PV)

    wmma::fragment<wmma::accumulator, 16, 16, 16, float> pacc[2];
#pragma unroll
    for (int i = 0; i < 2; i++) wmma::fill_fragment(pacc[i], 0.0f);

    float rs[8];
#pragma unroll
    for (int i = 0; i < 8; i++) rs[i] = 0.f;

#pragma unroll 1
    for (int c = 0; c < 8; c++) {
        const int l0 = c * 128;

        // issue vb_c into s_v (overlaps QK mma)
#pragma unroll
        for (int i = 0; i < 4; i++) {
            int e = i * 256 + tid;
            int r = e >> 3, c8 = e & 7;
            cp_async16(s_v + r * KLDS + c8 * 8,
                       vb + (size_t)(l0 + r) * OUT_ + c8 * 8);
        }
        cp_commit();
        cp_wait1();          // kb_c (and q on first iter) arrived
        __syncthreads();

        // ---- QK mma fp16: E tile 32x32 per warp, 4 k-steps of 16 ----
        wmma::fragment<wmma::accumulator, 16, 16, 16, float> eacc[2][2];
#pragma unroll
        for (int i = 0; i < 2; i++)
#pragma unroll
            for (int j = 0; j < 2; j++)
                wmma::fill_fragment(eacc[i][j], 0.0f);

#pragma unroll
        for (int ks = 0; ks < 4; ks++) {
            const int k = ks * 16;
            wmma::fragment<wmma::matrix_a, 16, 16, 16, __half, wmma::row_major> a[2];
            wmma::fragment<wmma::matrix_b, 16, 16, 16, __half, wmma::col_major> b[2];
#pragma unroll
            for (int i = 0; i < 2; i++)
                wmma::load_matrix_sync(a[i], s_q + (ewr * 32 + i * 16) * QLDS + k, QLDS);
#pragma unroll
            for (int j = 0; j < 2; j++)
                wmma::load_matrix_sync(b[j], s_k + (ewc * 32 + j * 16) * KLDS + k, KLDS);
#pragma unroll
            for (int i = 0; i < 2; i++)
#pragma unroll
                for (int j = 0; j < 2; j++)
                    wmma::mma_sync(eacc[i][j], a[i], b[j], eacc[i][j]);
        }

        // exp -> fp16, park in s_e
#pragma unroll
        for (int i = 0; i < 2; i++)
#pragma unroll
            for (int j = 0; j < 2; j++) {
                wmma::fragment<wmma::accumulator, 16, 16, 16, __half> eh;
#pragma unroll
                for (int t = 0; t < eacc[i][j].num_elements; t++)
                    eh.x[t] = __float2half(__expf(eacc[i][j].x[t] * 0.125f));
                wmma::store_matrix_sync(
                    s_e + (ewr * 32 + i * 16) * ELDS + ewc * 32 + j * 16,
                    eh, ELDS, wmma::mem_row_major);
            }
        __syncthreads();     // s_e ready; s_k free

        // issue kb_{c+1} into s_k (overlaps rowsum + PV mma)
        if (c < 7) {
            const __half* src = kb + (size_t)(l0 + 128) * KQ_;
#pragma unroll
            for (int i = 0; i < 4; i++) {
                int e = i * 256 + tid;
                int r = e >> 3, c8 = e & 7;
                cp_async16(s_k + r * KLDS + c8 * 8, src + (size_t)r * KQ_ + c8 * 8);
            }
            cp_commit();
        }

        // ---- rowsums + unnormalized attn write (warp w owns rows w*8..w*8+7)
#pragma unroll
        for (int i = 0; i < 8; i++) {
            const int r = w * 8 + i;
            const __half2* hrow = (const __half2*)(s_e + r * ELDS);
            float* arow = attn_out + (size_t)r * L_ + l0;
            float2 p0 = __half22float2(hrow[lane]);
            float2 p1 = __half22float2(hrow[32 + lane]);
            rs[i] += (p0.x + p0.y) + (p1.x + p1.y);
            *(float2*)(arow + 2 * lane)      = p0;
            *(float2*)(arow + 64 + 2 * lane) = p1;
        }

        if (c < 7) cp_wait1(); else cp_wait0();   // vb_c arrived
        __syncthreads();

        // ---- PV mma fp16: result tile 32x16 per warp, 8 k-steps of 16 ----
#pragma unroll
        for (int ks = 0; ks < 8; ks++) {
            const int k = ks * 16;
            wmma::fragment<wmma::matrix_a, 16, 16, 16, __half, wmma::row_major> a[2];
            wmma::fragment<wmma::matrix_b, 16, 16, 16, __half, wmma::row_major> b;
#pragma unroll
            for (int i = 0; i < 2; i++)
                wmma::load_matrix_sync(a[i], s_e + (ewr * 32 + i * 16) * ELDS + k, ELDS);
            wmma::load_matrix_sync(b, s_v + k * KLDS + ewc * 16, KLDS);
#pragma unroll
            for (int i = 0; i < 2; i++)
                wmma::mma_sync(pacc[i], a[i], b, pacc[i]);
        }
        __syncthreads();     // s_e / s_v free for next chunk
    }

    // ---- epilogue: rowsum reduce ----
#pragma unroll
    for (int i = 0; i < 8; i++) {
        float s = rs[i];
#pragma unroll
        for (int off = 16; off; off >>= 1)
            s += __shfl_xor_sync(0xffffffffu, s, off);
        if (lane == 0) s_inv[w * 8 + i] = 1.0f / s;
    }
    // park PV accumulators as float [64][68] in the s_e region (17,408 B fits)
    float* s_red = (float*)s_e;
#pragma unroll
    for (int i = 0; i < 2; i++)
        wmma::store_matrix_sync(s_red + (ewr * 32 + i * 16) * 68 + ewc * 16,
                                pacc[i], 68, wmma::mem_row_major);
    __syncthreads();

    // scaled result write: out[(b0+r)*N*64 + n*64 + c]  (1024 float4s)
#pragma unroll
    for (int it = 0; it < 4; it++) {
        int e = it * 256 + tid;
        int r = e >> 4, c4 = e & 15;
        const float inv = s_inv[r];
        float4 v = *(float4*)(s_red + r * 68 + c4 * 4);
        v.x *= inv; v.y *= inv; v.z *= inv; v.w *= inv;
        *(float4*)(out + ((size_t)(b0 + r) * N_ + n) * OUT_ + c4 * 4) = v;
    }

    // in-place attn normalization (64 x 1024 RMW, coalesced)
#pragma unroll 1
    for (int it = 0; it < 64; it++) {
        int e = it * 256 + tid;
        int r = e >> 8, c4 = e & 255;
        const float inv = s_inv[r];
        float4* p = (float4*)(attn_out + (size_t)r * L_ + c4 * 4);
        float4 v = *p;
        v.x *= inv; v.y *= inv; v.z *= inv; v.w *= inv;
        *p = v;
    }
}

// ---------------------------------------------------------------------------
extern "C" void kernel_launch(void* const* d_in, const int* in_sizes, int n_in,
                              void* d_out, int out_size)
{
    const float* queries = (const float*)d_in[0];
    const float* keys    = (const float*)d_in[1];
    const float* values  = (const float*)d_in[2];
    const float* Wq      = (const float*)d_in[3];
    const float* Wk      = (const float*)d_in[4];
    const float* Wv      = (const float*)d_in[5];
    float* out = (float*)d_out;

    cudaFuncSetAttribute(attn_kernel,
                         cudaFuncAttributeMaxDynamicSharedMemorySize, ATTN_SMEM);
    cudaFuncSetAttribute(proj_fp16_kernel,
                         cudaFuncAttributeMaxDynamicSharedMemorySize, PROJ_SMEM);

    __half *kbuf_ptr, *vbuf_ptr;
    cudaGetSymbolAddress((void**)&kbuf_ptr, g_kbuf);
    cudaGetSymbolAddress((void**)&vbuf_ptr, g_vbuf);

    // K1: combined key/value projections + fused q projection (fp16)
    dim3 pgrid((N_ * L_) / 128, 2);   // (2048, 2)
    proj_fp16_kernel<<<pgrid, 256, PROJ_SMEM>>>(queries, keys, values,
                                                Wq, Wk, Wv, kbuf_ptr, vbuf_ptr);

    // K2: fused attention (64-row CTAs, 2 CTAs/SM)
    dim3 grid(B_ / 64, N_);   // (4, 256)
    attn_kernel<<<grid, 256, ATTN_SMEM>>>(out);
}

// round 16
// speedup vs baseline: 4.1605x; 1.2992x over previous
#include <cuda_runtime.h>
#include <cuda_fp16.h>
#include <cuda_bf16.h>
#include <cstdint>
#include <mma.h>

using namespace nvcuda;

// Problem constants
#define B_  256
#define N_  256
#define L_  1024
#define D_  256
#define KQ_ 64
#define OUT_ 64

#define RESULT_ELEMS (B_ * N_ * OUT_)   // 4,194,304

// Scratch (device globals: allocation-free per harness rules) — fp16
__device__ __half g_q[B_ * KQ_];
__device__ __half g_kbuf[(size_t)N_ * L_ * KQ_];  // 33.5 MB
__device__ __half g_vbuf[(size_t)N_ * L_ * OUT_]; // 33.5 MB

// ---------------------------------------------------------------------------
// cp.async helpers (16B)
// ---------------------------------------------------------------------------
__device__ __forceinline__ void cp_async16(void* smem_dst, const void* gsrc)
{
    unsigned int s = (unsigned int)__cvta_generic_to_shared(smem_dst);
    asm volatile("cp.async.ca.shared.global [%0], [%1], 16;\n" :: "r"(s), "l"(gsrc));
}
__device__ __forceinline__ void cp_commit()
{
    asm volatile("cp.async.commit_group;\n");
}
__device__ __forceinline__ void cp_wait1()
{
    asm volatile("cp.async.wait_group 1;\n");
}
__device__ __forceinline__ void cp_wait0()
{
    asm volatile("cp.async.wait_group 0;\n");
}

// ---------------------------------------------------------------------------
// K1: combined K/V projection, fp16 datapath + fused qproj (unchanged, ~146us)
// ---------------------------------------------------------------------------
#define PWLD 72
#define PXLD 40
#define PXSTG (128 * PXLD)
#define PROJ_SMEM ((D_ * PWLD + 2 * PXSTG) * 2)   // 57,344 B

__global__ __launch_bounds__(256, 3)
void proj_fp16_kernel(const float* __restrict__ queries,
                      const float* __restrict__ keys,
                      const float* __restrict__ values,
                      const float* __restrict__ Wq,
                      const float* __restrict__ Wk,
                      const float* __restrict__ Wv,
                      __half* __restrict__ kbuf,
                      __half* __restrict__ vbuf)
{
    const int tid = threadIdx.x;

    if (blockIdx.y == 0 && blockIdx.x < 16) {
        const int base = blockIdx.x * 1024;
#pragma unroll
        for (int i = 0; i < 4; i++) {
            int o = base + i * 256 + tid;
            int b = o >> 6, j = o & 63;
            float acc = 0.f;
            const float* qrow = queries + b * D_;
            const float* wcol = Wq + j;
#pragma unroll 8
            for (int d = 0; d < D_; d++)
                acc += qrow[d] * wcol[(size_t)d * KQ_];
            g_q[o] = __float2half(acc);
        }
    }

    const float* X = (blockIdx.y == 0) ? keys : values;
    const float* W = (blockIdx.y == 0) ? Wk : Wv;
    __half*      Y = (blockIdx.y == 0) ? kbuf : vbuf;

    extern __shared__ __half psm[];
    __half* s_w = psm;               // [256][PWLD]
    __half* s_x = psm + D_ * PWLD;   // [2][128][PXLD]

    const int w  = tid >> 5;
    const int wr = w >> 1;
    const int wc = w & 1;
    const size_t row0 = (size_t)blockIdx.x * 128;

#pragma unroll
    for (int i = 0; i < 16; i++) {
        int f = i * 256 + tid;
        int r = f >> 4, c4 = f & 15;
        float4 v = *(const float4*)(W + (size_t)r * KQ_ + c4 * 4);
        __half2 h0 = __floats2half2_rn(v.x, v.y);
        __half2 h1 = __floats2half2_rn(v.z, v.w);
        *(uint2*)(s_w + r * PWLD + c4 * 4) = make_uint2(
            *(unsigned int*)&h0, *(unsigned int*)&h1);
    }

    const int xr = tid >> 1;
    const int xh = tid & 1;
    const float* xrow = X + (row0 + xr) * D_ + xh * 16;

    float4 rx[4];
#pragma unroll
    for (int i = 0; i < 4; i++)
        rx[i] = *(const float4*)(xrow + i * 4);

    wmma::fragment<wmma::accumulator, 16, 16, 16, float> acc[2][2];
#pragma unroll
    for (int i = 0; i < 2; i++)
#pragma unroll
        for (int j = 0; j < 2; j++)
            wmma::fill_fragment(acc[i][j], 0.0f);

#pragma unroll 1
    for (int c = 0; c < 8; c++) {
        __half* xb = s_x + (c & 1) * PXSTG;
#pragma unroll
        for (int i = 0; i < 4; i++) {
            __half2 h0 = __floats2half2_rn(rx[i].x, rx[i].y);
            __half2 h1 = __floats2half2_rn(rx[i].z, rx[i].w);
            *(uint2*)(xb + xr * PXLD + xh * 16 + i * 4) = make_uint2(
                *(unsigned int*)&h0, *(unsigned int*)&h1);
        }
        __syncthreads();

        if (c < 7) {
#pragma unroll
            for (int i = 0; i < 4; i++)
                rx[i] = *(const float4*)(xrow + (c + 1) * 32 + i * 4);
        }

        const int k0 = c * 32;
#pragma unroll
        for (int ks = 0; ks < 2; ks++) {
            const int k = ks * 16;
            wmma::fragment<wmma::matrix_a, 16, 16, 16, __half, wmma::row_major> a[2];
            wmma::fragment<wmma::matrix_b, 16, 16, 16, __half, wmma::row_major> b[2];
#pragma unroll
            for (int i = 0; i < 2; i++)
                wmma::load_matrix_sync(a[i], xb + (wr * 32 + i * 16) * PXLD + k, PXLD);
#pragma unroll
            for (int j = 0; j < 2; j++)
                wmma::load_matrix_sync(b[j], s_w + (k0 + k) * PWLD + wc * 32 + j * 16, PWLD);
#pragma unroll
            for (int i = 0; i < 2; i++)
#pragma unroll
                for (int j = 0; j < 2; j++)
                    wmma::mma_sync(acc[i][j], a[i], b[j], acc[i][j]);
        }
        __syncthreads();
    }

#pragma unroll
    for (int i = 0; i < 2; i++)
#pragma unroll
        for (int j = 0; j < 2; j++) {
            wmma::fragment<wmma::accumulator, 16, 16, 16, __half> h;
#pragma unroll
            for (int t = 0; t < acc[i][j].num_elements; t++)
                h.x[t] = __float2half(acc[i][j].x[t]);
            wmma::store_matrix_sync(Y + (row0 + wr * 32 + i * 16) * KQ_ + wc * 32 + j * 16,
                                    h, KQ_, wmma::mem_row_major);
        }
}

// ---------------------------------------------------------------------------
// K2: fused streaming attention, fp16, two-pass recompute softmax.
// Block = 64 b-rows x one n, 256 threads, 2 CTAs/SM.
// Pass 1: QK mma + exp + register rowsums (fragment row mapping).
// Pass 2: QK mma again + exp; write attn normalized ONCE (direct frag store);
//         fp16 E -> s_e; PV mma; epilogue scales out by 1/rowsum.
// Accumulator f32 fragment row mapping (m16n8k16 pair):
//   elements {0,1,4,5} -> row (lane>>2); {2,3,6,7} -> row (lane>>2)+8.
// ---------------------------------------------------------------------------
#define QLDS 72    // halves
#define KLDS 72
#define ELDS 136
#define SQ_OFF 0
#define SK_OFF (64 * QLDS)                  //  4608 halves
#define SV_OFF (SK_OFF + 128 * KLDS)        // 13824
#define SE_OFF (SV_OFF + 128 * KLDS)        // 23040
#define SE_HALVES (64 * ELDS)               //  8704
#define SI_OFF (SE_OFF + SE_HALVES)         // 31744 halves (8B aligned)
#define ATTN_SMEM ((SI_OFF) * 2 + 64 * 4)   // 63,744 B

__global__ __launch_bounds__(256, 2)
void attn_kernel(float* __restrict__ out)
{
    extern __shared__ __half hsm[];
    __half* s_q   = hsm + SQ_OFF;   // [64][QLDS] q tile
    __half* s_k   = hsm + SK_OFF;   // [128][KLDS] kb chunk (pass2) / kb ping (pass1)
    __half* s_v   = hsm + SV_OFF;   // [128][KLDS] vb chunk (pass2) / kb pong (pass1)
    __half* s_e   = hsm + SE_OFF;   // [64][ELDS] E chunk (fp16)
    float*  s_inv = (float*)(hsm + SI_OFF);  // [64] rowsum -> 1/rowsum

    const int n   = blockIdx.y;
    const int b0  = blockIdx.x * 64;
    const int tid = threadIdx.x;
    const int w    = tid >> 5;      // 0..7
    const int lane = tid & 31;

    const __half* kb = g_kbuf + (size_t)n * L_ * KQ_;
    const __half* vb = g_vbuf + (size_t)n * L_ * OUT_;
    float* attn_out = out + RESULT_ELEMS + ((size_t)n * B_ + b0) * L_;

    const int ewr = w >> 2;   // 0..1 (32-row band)
    const int ewc = w & 3;    // 0..3 (32-col band QK / 16-col PV)

    // Prologue: stage q tile + kb chunk 0 into s_k.
#pragma unroll
    for (int i = 0; i < 2; i++) {
        int e = i * 256 + tid;
        int r = e >> 3, c8 = e & 7;
        cp_async16(s_q + r * QLDS + c8 * 8, g_q + (size_t)(b0 + r) * KQ_ + c8 * 8);
    }
#pragma unroll
    for (int i = 0; i < 4; i++) {
        int e = i * 256 + tid;
        int r = e >> 3, c8 = e & 7;
        cp_async16(s_k + r * KLDS + c8 * 8, kb + (size_t)r * KQ_ + c8 * 8);
    }
    cp_commit();

    if (tid < 64) s_inv[tid] = 0.f;

    // =================== PASS 1: rowsums only ===================
    float sumA[2] = {0.f, 0.f};
    float sumB[2] = {0.f, 0.f};

#pragma unroll 1
    for (int c = 0; c < 8; c++) {
        cp_wait0();
        __syncthreads();                 // kb_c visible; previous buffer free

        __half* buf   = (c & 1) ? s_v : s_k;
        __half* other = (c & 1) ? s_k : s_v;
        if (c < 7) {
            const __half* src = kb + (size_t)(c + 1) * 128 * KQ_;
#pragma unroll
            for (int i = 0; i < 4; i++) {
                int e = i * 256 + tid;
                int r = e >> 3, c8 = e & 7;
                cp_async16(other + r * KLDS + c8 * 8, src + (size_t)r * KQ_ + c8 * 8);
            }
            cp_commit();
        }

        wmma::fragment<wmma::accumulator, 16, 16, 16, float> eacc[2][2];
#pragma unroll
        for (int i = 0; i < 2; i++)
#pragma unroll
            for (int j = 0; j < 2; j++)
                wmma::fill_fragment(eacc[i][j], 0.0f);

#pragma unroll
        for (int ks = 0; ks < 4; ks++) {
            const int k = ks * 16;
            wmma::fragment<wmma::matrix_a, 16, 16, 16, __half, wmma::row_major> a[2];
            wmma::fragment<wmma::matrix_b, 16, 16, 16, __half, wmma::col_major> b[2];
#pragma unroll
            for (int i = 0; i < 2; i++)
                wmma::load_matrix_sync(a[i], s_q + (ewr * 32 + i * 16) * QLDS + k, QLDS);
#pragma unroll
            for (int j = 0; j < 2; j++)
                wmma::load_matrix_sync(b[j], buf + (ewc * 32 + j * 16) * KLDS + k, KLDS);
#pragma unroll
            for (int i = 0; i < 2; i++)
#pragma unroll
                for (int j = 0; j < 2; j++)
                    wmma::mma_sync(eacc[i][j], a[i], b[j], eacc[i][j]);
        }

        // exp + fragment-level rowsum accumulation
#pragma unroll
        for (int i = 0; i < 2; i++)
#pragma unroll
            for (int j = 0; j < 2; j++) {
                float e0 = __expf(eacc[i][j].x[0] * 0.125f);
                float e1 = __expf(eacc[i][j].x[1] * 0.125f);
                float e2 = __expf(eacc[i][j].x[2] * 0.125f);
                float e3 = __expf(eacc[i][j].x[3] * 0.125f);
                float e4 = __expf(eacc[i][j].x[4] * 0.125f);
                float e5 = __expf(eacc[i][j].x[5] * 0.125f);
                float e6 = __expf(eacc[i][j].x[6] * 0.125f);
                float e7 = __expf(eacc[i][j].x[7] * 0.125f);
                sumA[i] += (e0 + e1) + (e4 + e5);
                sumB[i] += (e2 + e3) + (e6 + e7);
            }
    }

    // quad-reduce (lanes sharing lane>>2) and deposit into s_inv via shared atomics
#pragma unroll
    for (int i = 0; i < 2; i++) {
        sumA[i] += __shfl_xor_sync(0xffffffffu, sumA[i], 1);
        sumA[i] += __shfl_xor_sync(0xffffffffu, sumA[i], 2);
        sumB[i] += __shfl_xor_sync(0xffffffffu, sumB[i], 1);
        sumB[i] += __shfl_xor_sync(0xffffffffu, sumB[i], 2);
        if ((lane & 3) == 0) {
            int rA = ewr * 32 + i * 16 + (lane >> 2);
            atomicAdd(&s_inv[rA], sumA[i]);
            atomicAdd(&s_inv[rA + 8], sumB[i]);
        }
    }
    __syncthreads();
    if (tid < 64) s_inv[tid] = 1.0f / s_inv[tid];
    __syncthreads();

    // per-thread inverse factors for this warp's fragment rows
    float invA[2], invB[2];
#pragma unroll
    for (int i = 0; i < 2; i++) {
        invA[i] = s_inv[ewr * 32 + i * 16 + (lane >> 2)];
        invB[i] = s_inv[ewr * 32 + i * 16 + 8 + (lane >> 2)];
    }

    // =================== PASS 2: attn write + PV ===================
    // restage kb chunk 0 into s_k
#pragma unroll
    for (int i = 0; i < 4; i++) {
        int e = i * 256 + tid;
        int r = e >> 3, c8 = e & 7;
        cp_async16(s_k + r * KLDS + c8 * 8, kb + (size_t)r * KQ_ + c8 * 8);
    }
    cp_commit();

    wmma::fragment<wmma::accumulator, 16, 16, 16, float> pacc[2];
#pragma unroll
    for (int i = 0; i < 2; i++) wmma::fill_fragment(pacc[i], 0.0f);

#pragma unroll 1
    for (int c = 0; c < 8; c++) {
        const int l0 = c * 128;

        // issue vb_c into s_v (overlaps QK mma)
#pragma unroll
        for (int i = 0; i < 4; i++) {
            int e = i * 256 + tid;
            int r = e >> 3, c8 = e & 7;
            cp_async16(s_v + r * KLDS + c8 * 8,
                       vb + (size_t)(l0 + r) * OUT_ + c8 * 8);
        }
        cp_commit();
        cp_wait1();          // kb_c arrived
        __syncthreads();

        // ---- QK mma fp16 ----
        wmma::fragment<wmma::accumulator, 16, 16, 16, float> eacc[2][2];
#pragma unroll
        for (int i = 0; i < 2; i++)
#pragma unroll
            for (int j = 0; j < 2; j++)
                wmma::fill_fragment(eacc[i][j], 0.0f);

#pragma unroll
        for (int ks = 0; ks < 4; ks++) {
            const int k = ks * 16;
            wmma::fragment<wmma::matrix_a, 16, 16, 16, __half, wmma::row_major> a[2];
            wmma::fragment<wmma::matrix_b, 16, 16, 16, __half, wmma::col_major> b[2];
#pragma unroll
            for (int i = 0; i < 2; i++)
                wmma::load_matrix_sync(a[i], s_q + (ewr * 32 + i * 16) * QLDS + k, QLDS);
#pragma unroll
            for (int j = 0; j < 2; j++)
                wmma::load_matrix_sync(b[j], s_k + (ewc * 32 + j * 16) * KLDS + k, KLDS);
#pragma unroll
            for (int i = 0; i < 2; i++)
#pragma unroll
                for (int j = 0; j < 2; j++)
                    wmma::mma_sync(eacc[i][j], a[i], b[j], eacc[i][j]);
        }

        // exp; fp16 unnormalized E -> s_e; normalized fp32 -> attn (direct store)
#pragma unroll
        for (int i = 0; i < 2; i++)
#pragma unroll
            for (int j = 0; j < 2; j++) {
                wmma::fragment<wmma::accumulator, 16, 16, 16, __half> eh;
#pragma unroll
                for (int t = 0; t < eacc[i][j].num_elements; t++) {
                    float e = __expf(eacc[i][j].x[t] * 0.125f);
                    eh.x[t] = __float2half(e);
                    // rows {0,1,4,5} -> lane>>2 ; {2,3,6,7} -> +8
                    eacc[i][j].x[t] = e * (((t & 2) == 0) ? invA[i] : invB[i]);
                }
                wmma::store_matrix_sync(
                    s_e + (ewr * 32 + i * 16) * ELDS + ewc * 32 + j * 16,
                    eh, ELDS, wmma::mem_row_major);
                wmma::store_matrix_sync(
                    attn_out + (size_t)(ewr * 32 + i * 16) * L_ + l0 + ewc * 32 + j * 16,
                    eacc[i][j], L_, wmma::mem_row_major);
            }
        __syncthreads();     // s_e ready; s_k free

        // issue kb_{c+1} into s_k (overlaps PV mma)
        if (c < 7) {
            const __half* src = kb + (size_t)(l0 + 128) * KQ_;
#pragma unroll
            for (int i = 0; i < 4; i++) {
                int e = i * 256 + tid;
                int r = e >> 3, c8 = e & 7;
                cp_async16(s_k + r * KLDS + c8 * 8, src + (size_t)r * KQ_ + c8 * 8);
            }
            cp_commit();
        }

        if (c < 7) cp_wait1(); else cp_wait0();   // vb_c arrived
        __syncthreads();

        // ---- PV mma fp16: result tile 32x16 per warp ----
#pragma unroll
        for (int ks = 0; ks < 8; ks++) {
            const int k = ks * 16;
            wmma::fragment<wmma::matrix_a, 16, 16, 16, __half, wmma::row_major> a[2];
            wmma::fragment<wmma::matrix_b, 16, 16, 16, __half, wmma::row_major> b;
#pragma unroll
            for (int i = 0; i < 2; i++)
                wmma::load_matrix_sync(a[i], s_e + (ewr * 32 + i * 16) * ELDS + k, ELDS);
            wmma::load_matrix_sync(b, s_v + k * KLDS + ewc * 16, KLDS);
#pragma unroll
            for (int i = 0; i < 2; i++)
                wmma::mma_sync(pacc[i], a[i], b, pacc[i]);
        }
        __syncthreads();     // s_e / s_v free for next chunk
    }

    // ---- epilogue: out = pacc * inv ----
    float* s_red = (float*)s_e;
#pragma unroll
    for (int i = 0; i < 2; i++)
        wmma::store_matrix_sync(s_red + (ewr * 32 + i * 16) * 68 + ewc * 16,
                                pacc[i], 68, wmma::mem_row_major);
    __syncthreads();

#pragma unroll
    for (int it = 0; it < 4; it++) {
        int e = it * 256 + tid;
        int r = e >> 4, c4 = e & 15;
        const float inv = s_inv[r];
        float4 v = *(float4*)(s_red + r * 68 + c4 * 4);
        v.x *= inv; v.y *= inv; v.z *= inv; v.w *= inv;
        *(float4*)(out + ((size_t)(b0 + r) * N_ + n) * OUT_ + c4 * 4) = v;
    }
}

// ---------------------------------------------------------------------------
extern "C" void kernel_launch(void* const* d_in, const int* in_sizes, int n_in,
                              void* d_out, int out_size)
{
    const float* queries = (const float*)d_in[0];
    const float* keys    = (const float*)d_in[1];
    const float* values  = (const float*)d_in[2];
    const float* Wq      = (const float*)d_in[3];
    const float* Wk      = (const float*)d_in[4];
    const float* Wv      = (const float*)d_in[5];
    float* out = (float*)d_out;

    cudaFuncSetAttribute(attn_kernel,
                         cudaFuncAttributeMaxDynamicSharedMemorySize, ATTN_SMEM);
    cudaFuncSetAttribute(proj_fp16_kernel,
                         cudaFuncAttributeMaxDynamicSharedMemorySize, PROJ_SMEM);

    __half *kbuf_ptr, *vbuf_ptr;
    cudaGetSymbolAddress((void**)&kbuf_ptr, g_kbuf);
    cudaGetSymbolAddress((void**)&vbuf_ptr, g_vbuf);

    // K1: combined key/value projections + fused q projection (fp16)
    dim3 pgrid((N_ * L_) / 128, 2);   // (2048, 2)
    proj_fp16_kernel<<<pgrid, 256, PROJ_SMEM>>>(queries, keys, values,
                                                Wq, Wk, Wv, kbuf_ptr, vbuf_ptr);

    // K2: fused attention, two-pass softmax (64-row CTAs)
    dim3 grid(B_ / 64, N_);   // (4, 256)
    attn_kernel<<<grid, 256, ATTN_SMEM>>>(out);
}